// round 13
// baseline (speedup 1.0000x reference)
#include <cuda_runtime.h>
#include <cstdint>

// ---------------- Problem-size constants (fixed instance) ----------------
#define N_ATOMS_MAX  100000
#define N_BONDS_MAX  200000
#define H_DIM        300
#define H4_DIM       75

#define BM 128
#define BN 128
#define KC 32            // K-chunk: 32 tf32 = 128B rows (SW128)
#define NTHR 256
#define TILE_U32 (BN * KC)       // 4096 u32 = 16KB per packed tile
#define TILE_BYTES (TILE_U32 * 4)

#define MAX_CB 3             // col blocks for N=300
#define NC_WI  5             // ceil(147/32)
#define NC_WH  10            // ceil(300/32)
#define NC_WO  14            // ceil(433/32)

// ---------------- Device scratch (static, allocation-free) ----------------
__device__ float g_inp [(size_t)N_BONDS_MAX * H_DIM];
__device__ float g_msgA[(size_t)N_BONDS_MAX * H_DIM];
__device__ float g_msgB[(size_t)N_BONDS_MAX * H_DIM];
__device__ float g_amsg[(size_t)N_ATOMS_MAX * H_DIM];
__device__ float g_ahid[(size_t)N_ATOMS_MAX * H_DIM];
__device__ __align__(1024) uint32_t g_packWi[(size_t)MAX_CB * NC_WI * TILE_U32];
__device__ __align__(1024) uint32_t g_packWh[(size_t)MAX_CB * NC_WH * TILE_U32];
__device__ __align__(1024) uint32_t g_packWo[(size_t)MAX_CB * NC_WO * TILE_U32];

// Arch-feature gate: tcgen05 exists only in arch-specific (sm_103a) passes.
#if defined(__CUDA_ARCH_FEAT_SM103_ALL) || defined(__CUDA_ARCH_FEAT_SM100_ALL) || defined(__CUDA_ARCH_SPECIFIC__)
#define USE_TC5 1
#else
#define USE_TC5 0
#endif

// ---------------- common helpers ----------------
__device__ __forceinline__ uint32_t f2tf(float f) {
    uint32_t u;
    asm("cvt.rna.tf32.f32 %0, %1;" : "=r"(u) : "f"(f));
    return u;
}
__device__ __forceinline__ uint32_t smem_u32(const void* p) {
    uint32_t a;
    asm("{ .reg .u64 t; cvta.to.shared.u64 t, %1; cvt.u32.u64 %0, t; }" : "=r"(a) : "l"(p));
    return a;
}
__device__ __forceinline__ uint32_t sw128(uint32_t off) { return off ^ ((off >> 3) & 0x70); }

#if USE_TC5
#define TMEM_COLS 128
// idesc: bit4 dtype=F32 | atype TF32=2 @7 | btype TF32=2 @10 | (N/8)@17 | (M/16)@24
#define MMA_IDESC ((1u<<4) | (2u<<7) | (2u<<10) | ((BN/8u)<<17) | ((BM/16u)<<24))

__device__ __forceinline__ bool elect_one() {
    uint32_t p;
    asm volatile("{ .reg .pred P; elect.sync _|P, 0xFFFFFFFF; selp.b32 %0, 1, 0, P; }" : "=r"(p));
    return p != 0;
}
__device__ __forceinline__ uint64_t make_desc_sw128(uint32_t addr) {
    return (uint64_t)((addr >> 4) & 0x3FFF)
         | ((uint64_t)1  << 16) | ((uint64_t)64 << 32)
         | ((uint64_t)1  << 46) | ((uint64_t)2  << 61);
}
__device__ __forceinline__ void tmem_alloc(uint32_t smem_dst, uint32_t ncols) {
    asm volatile("tcgen05.alloc.cta_group::1.sync.aligned.shared::cta.b32 [%0], %1;"
                 :: "r"(smem_dst), "r"(ncols) : "memory");
}
__device__ __forceinline__ void tmem_relinquish() {
    asm volatile("tcgen05.relinquish_alloc_permit.cta_group::1.sync.aligned;");
}
__device__ __forceinline__ void tmem_dealloc(uint32_t tmem, uint32_t ncols) {
    asm volatile("tcgen05.dealloc.cta_group::1.sync.aligned.b32 %0, %1;" :: "r"(tmem), "r"(ncols));
}
__device__ __forceinline__ void mbar_init(uint32_t mb, uint32_t cnt) {
    asm volatile("mbarrier.init.shared.b64 [%0], %1;" :: "r"(mb), "r"(cnt) : "memory");
}
__device__ __forceinline__ void mbar_expect_tx(uint32_t mb, uint32_t bytes) {
    asm volatile("mbarrier.arrive.expect_tx.shared.b64 _, [%0], %1;"
                 :: "r"(mb), "r"(bytes) : "memory");
}
__device__ __forceinline__ void bulk_copy_g2s(uint32_t dst_smem, const void* src_gmem,
                                              uint32_t bytes, uint32_t mb) {
    asm volatile("cp.async.bulk.shared::cta.global.mbarrier::complete_tx::bytes "
                 "[%0], [%1], %2, [%3];"
                 :: "r"(dst_smem), "l"(src_gmem), "r"(bytes), "r"(mb) : "memory");
}
__device__ __forceinline__ void mbar_wait(uint32_t mb, uint32_t parity) {
    asm volatile(
        "{\n\t.reg .pred P;\n\t"
        "WL_%=:\n\t"
        "mbarrier.try_wait.parity.acquire.cta.shared::cta.b64 P, [%0], %1, 0x989680;\n\t"
        "@!P bra WL_%=;\n\t}"
        :: "r"(mb), "r"(parity) : "memory");
}
__device__ __forceinline__ void mma_tf32_ss(uint32_t d, uint64_t a, uint64_t b,
                                            uint32_t idesc, uint32_t en) {
    asm volatile(
        "{\n\t.reg .pred p;\n\tsetp.ne.u32 p, %4, 0;\n\t"
        "tcgen05.mma.cta_group::1.kind::tf32 [%0], %1, %2, %3, {%5, %5, %5, %5}, p;\n\t}"
        :: "r"(d), "l"(a), "l"(b), "r"(idesc), "r"(en), "r"(0u) : "memory");
}
__device__ __forceinline__ void mma_commit(uint32_t mb) {
    asm volatile("tcgen05.commit.cta_group::1.mbarrier::arrive::one.shared::cluster.b64 [%0];"
                 :: "r"(mb) : "memory");
}
__device__ __forceinline__ void ldtm_x32(uint32_t* r, uint32_t tmem) {
    asm volatile(
        "tcgen05.ld.sync.aligned.32x32b.x32.b32 "
        "{%0,%1,%2,%3,%4,%5,%6,%7,%8,%9,%10,%11,%12,%13,%14,%15,"
        "%16,%17,%18,%19,%20,%21,%22,%23,%24,%25,%26,%27,%28,%29,%30,%31}, [%32];"
        : "=r"(r[0]), "=r"(r[1]), "=r"(r[2]), "=r"(r[3]), "=r"(r[4]), "=r"(r[5]), "=r"(r[6]), "=r"(r[7]),
          "=r"(r[8]), "=r"(r[9]), "=r"(r[10]), "=r"(r[11]), "=r"(r[12]), "=r"(r[13]), "=r"(r[14]), "=r"(r[15]),
          "=r"(r[16]), "=r"(r[17]), "=r"(r[18]), "=r"(r[19]), "=r"(r[20]), "=r"(r[21]), "=r"(r[22]), "=r"(r[23]),
          "=r"(r[24]), "=r"(r[25]), "=r"(r[26]), "=r"(r[27]), "=r"(r[28]), "=r"(r[29]), "=r"(r[30]), "=r"(r[31])
        : "r"(tmem));
}
__device__ __forceinline__ void tmem_wait_ld() {
    asm volatile("tcgen05.wait::ld.sync.aligned;" ::: "memory");
}
__device__ __forceinline__ void tc5_fence_after() {
    asm volatile("tcgen05.fence::after_thread_sync;" ::: "memory");
}
__device__ __forceinline__ void tc5_fence_before() {
    asm volatile("tcgen05.fence::before_thread_sync;" ::: "memory");
}
__device__ __forceinline__ void fence_proxy_async_cta() {
    asm volatile("fence.proxy.async.shared::cta;" ::: "memory");
}
#endif // USE_TC5

// ---------------- mma.sync fallback helpers ----------------
#define BKF 16
#define SKF 20
__device__ __forceinline__ void mma8(float* c, const uint32_t* a, const uint32_t* b) {
    asm volatile(
        "mma.sync.aligned.m16n8k8.row.col.f32.tf32.tf32.f32 "
        "{%0,%1,%2,%3}, {%4,%5,%6,%7}, {%8,%9}, {%0,%1,%2,%3};\n"
        : "+f"(c[0]), "+f"(c[1]), "+f"(c[2]), "+f"(c[3])
        : "r"(a[0]), "r"(a[1]), "r"(a[2]), "r"(a[3]), "r"(b[0]), "r"(b[1]));
}

// ---- Pack W[K][N] into swizzled tf32 tiles: dst[cb*NC + ci][sw128 layout] ----
__global__ void pack_W_kernel(const float* __restrict__ W, uint32_t* __restrict__ dst,
                              int K, int N, int NC)
{
    const int tile = blockIdx.x;          // cb * NC + ci
    const int cb = tile / NC, ci = tile - cb * NC;
    const int colBase = cb * BN, kk = ci * KC;
    uint32_t* out = dst + (size_t)tile * TILE_U32;
    for (int i = threadIdx.x; i < TILE_U32; i += blockDim.x) {
        const int n = i >> 5, k = i & 31;
        const int gk = kk + k, gc = colBase + n;
        float v = (gk < K && gc < N) ? W[(size_t)gk * N + gc] : 0.f;
        out[sw128((uint32_t)(n << 7) + (uint32_t)(k << 2)) >> 2] = f2tf(v);
    }
}

// ---------------- Unified GEMM ----------------
// MODE 0: out0 = A0 @ W
// MODE 1: out0 = relu(aux + (A0[b2a[r]] - ra1(A1[b2revb[r]])) @ W)  ra1 = relu if RELU_A1
// MODE 2: out0 = relu([A0 | A1] @ W + aux(bias))
// Wp = pre-packed W tiles (tcgen05 path); W = raw weights (fallback path).
template<int MODE, int RELU_A1>
__global__ __launch_bounds__(NTHR, 4)
void gemm_tc5(const float* __restrict__ A0, const float* __restrict__ A1,
              const int* __restrict__ b2a, const int* __restrict__ b2revb,
              const float* __restrict__ W, const uint32_t* __restrict__ Wp,
              const float* __restrict__ aux, float* __restrict__ out0,
              int M, int K, int N, int AF)
{
    const int tid  = threadIdx.x;
    const int lane = tid & 31;
    const int wid  = tid >> 5;
    const int rowBase = blockIdx.y * BM;
    const int colBase = blockIdx.x * BN;

    __shared__ const float* s_p0[BM];
    __shared__ const float* s_p1[BM];
    if (tid < BM) {
        int gr = rowBase + tid;
        if (gr >= M) gr = M - 1;
        if (MODE == 0) {
            s_p0[tid] = A0 + (size_t)gr * K;
        } else if (MODE == 1) {
            s_p0[tid] = A0 + (size_t)b2a[gr] * K;
            s_p1[tid] = A1 + (size_t)b2revb[gr] * K;
        } else {
            s_p0[tid] = A0 + (size_t)gr * AF;
            s_p1[tid] = A1 + (size_t)gr * (K - AF);
        }
    }

#if USE_TC5
    // ====== tcgen05 tf32: reg-prefetched A + double-buffered TMA pre-packed B ======
    __shared__ alignas(1024) uint32_t sA[BM * KC];        // 16 KB
    __shared__ alignas(1024) uint32_t sB[2][BN * KC];     // 32 KB
    __shared__ uint32_t s_tmem;
    __shared__ alignas(8) uint64_t s_mbar_mma;
    __shared__ alignas(8) uint64_t s_mbar_tma[2];

    if (wid == 0) {
        tmem_alloc(smem_u32(&s_tmem), TMEM_COLS);
        tmem_relinquish();
    }
    if (tid == 0) {
        mbar_init(smem_u32(&s_mbar_mma), 1);
        mbar_init(smem_u32(&s_mbar_tma[0]), 1);
        mbar_init(smem_u32(&s_mbar_tma[1]), 1);
    }
    __syncthreads();

    const uint32_t tmem = s_tmem;
    const uint32_t mbM  = smem_u32(&s_mbar_mma);
    const uint32_t mbT[2] = { smem_u32(&s_mbar_tma[0]), smem_u32(&s_mbar_tma[1]) };
    const uint32_t sB_addr[2] = { smem_u32(sB[0]), smem_u32(sB[1]) };
    const uint64_t adesc = make_desc_sw128(smem_u32(sA));
    const uint64_t bdesc[2] = { make_desc_sw128(sB_addr[0]), make_desc_sw128(sB_addr[1]) };

    uint32_t phM = 0;
    uint32_t phT[2] = {0u, 0u};
    const int NC = (K + KC - 1) / KC;
    const uint32_t* wp = Wp + (size_t)blockIdx.x * NC * TILE_U32;

    // precomputed conflict-free swizzled store index base (proof: off[7:9] = wid)
    const uint32_t sa_lane = (uint32_t)(lane ^ (wid << 2));

    // ---- prologue: issue TMA for B(0) ----
    if (wid == 0 && elect_one()) {
        mbar_expect_tx(mbT[0], TILE_BYTES);
        bulk_copy_g2s(sB_addr[0], wp, TILE_BYTES, mbT[0]);
    }

    // ---- A prefetch: 16 regs/thread, rows r = p*8 + wid, col = kk + lane ----
    float ra[16];
    {
        const int gk = lane;
        const bool kok = gk < K;
        #pragma unroll
        for (int p = 0; p < 16; ++p) {
            const int r = (p << 3) + wid;
            float v = 0.f;
            if (kok) {
                if (MODE == 0)      v = s_p0[r][gk];
                else if (MODE == 1) {
                    float a1 = s_p1[r][gk];
                    if (RELU_A1) a1 = fmaxf(a1, 0.f);
                    v = s_p0[r][gk] - a1;
                }
                else                v = (gk < AF) ? s_p0[r][gk] : s_p1[r][gk - AF];
            }
            ra[p] = v;
        }
    }

    for (int ci = 0; ci < NC; ++ci) {
        const int b = ci & 1;
        if (ci > 0) { mbar_wait(mbM, phM); phM ^= 1u; }   // frees sA and buf[(ci+1)&1]

        // ---- issue TMA for B(ci+1) into the buffer just freed by MMA(ci-1) ----
        if (ci + 1 < NC && wid == 0 && elect_one()) {
            const int b1 = (ci + 1) & 1;
            mbar_expect_tx(mbT[b1], TILE_BYTES);
            bulk_copy_g2s(sB_addr[b1], wp + (size_t)(ci + 1) * TILE_U32, TILE_BYTES, mbT[b1]);
        }

        // ---- write prefetched A regs -> smem (tf32 via cvt.rna) ----
        #pragma unroll
        for (int p = 0; p < 16; ++p) {
            const int r = (p << 3) + wid;
            sA[((uint32_t)r << 5) + sa_lane] = f2tf(ra[p]);
        }

        // ---- wait for B(ci) (issued a full round earlier), then sync A visibility ----
        mbar_wait(mbT[b], phT[b]); phT[b] ^= 1u;
        __syncthreads();

        if (wid == 0) {
            fence_proxy_async_cta();
            if (elect_one()) {
                #pragma unroll
                for (int ks = 0; ks < 4; ++ks) {
                    const uint32_t en = (ci > 0 || ks > 0) ? 1u : 0u;
                    mma_tf32_ss(tmem, adesc + (uint64_t)(ks * 2), bdesc[b] + (uint64_t)(ks * 2),
                                MMA_IDESC, en);
                }
                mma_commit(mbM);
            }
        }

        // ---- prefetch next A chunk (overlaps MMA + next wait) ----
        if (ci + 1 < NC) {
            const int gk = (ci + 1) * KC + lane;
            const bool kok = gk < K;
            #pragma unroll
            for (int p = 0; p < 16; ++p) {
                const int r = (p << 3) + wid;
                float v = 0.f;
                if (kok) {
                    if (MODE == 0)      v = s_p0[r][gk];
                    else if (MODE == 1) {
                        float a1 = s_p1[r][gk];
                        if (RELU_A1) a1 = fmaxf(a1, 0.f);
                        v = s_p0[r][gk] - a1;
                    }
                    else                v = (gk < AF) ? s_p0[r][gk] : s_p1[r][gk - AF];
                }
                ra[p] = v;
            }
        }
    }

    mbar_wait(mbM, phM);

    // ---- epilogue: warp w -> rows (w&3)*32+lane ; cols (w>>2)*64..+63 ----
    tc5_fence_after();
    const int gr = rowBase + (wid & 3) * 32 + lane;
    const bool rok = gr < M;
    const int cb0 = (wid >> 2) * 2;

    #pragma unroll
    for (int bb = 0; bb < 2; ++bb) {
        const int b = cb0 + bb;
        uint32_t d[32];
        ldtm_x32(d, tmem + (uint32_t)(b * 32));
        tmem_wait_ld();
        if (rok) {
            const int cbase = colBase + b * 32;
            #pragma unroll
            for (int j = 0; j < 32; j += 4) {
                const int c = cbase + j;
                if (c + 3 < N) {
                    const size_t o = (size_t)gr * N + c;
                    float4 v = make_float4(__uint_as_float(d[j]), __uint_as_float(d[j+1]),
                                           __uint_as_float(d[j+2]), __uint_as_float(d[j+3]));
                    if (MODE == 0) {
                        *(float4*)(out0 + o) = v;
                    } else if (MODE == 1) {
                        float4 i4 = *(const float4*)(aux + o);
                        *(float4*)(out0 + o) = make_float4(
                            fmaxf(i4.x+v.x,0.f), fmaxf(i4.y+v.y,0.f),
                            fmaxf(i4.z+v.z,0.f), fmaxf(i4.w+v.w,0.f));
                    } else {
                        *(float4*)(out0 + o) = make_float4(
                            fmaxf(v.x+aux[c],0.f),   fmaxf(v.y+aux[c+1],0.f),
                            fmaxf(v.z+aux[c+2],0.f), fmaxf(v.w+aux[c+3],0.f));
                    }
                } else {
                    #pragma unroll
                    for (int q = 0; q < 4; ++q) {
                        const int cc = c + q;
                        if (cc >= N) break;
                        const size_t o = (size_t)gr * N + cc;
                        const float v = __uint_as_float(d[j + q]);
                        if (MODE == 0)      { out0[o] = v; }
                        else if (MODE == 1) { out0[o] = fmaxf(aux[o] + v, 0.f); }
                        else                { out0[o] = fmaxf(v + aux[cc], 0.f); }
                    }
                }
            }
        }
    }
    tc5_fence_before();
    __syncthreads();
    if (wid == 0) tmem_dealloc(tmem, TMEM_COLS);

#else
    // ================= mma.sync tf32 fallback (8 warps) =================
    __shared__ uint32_t As[BM][SKF];
    __shared__ uint32_t Bs[BN][SKF];
    __syncthreads();

    const int wm = wid >> 2, wn = wid & 3;
    const int g = lane >> 2, tg = lane & 3;

    float acc[4][4][4] = {};

    const int arow = tid >> 1;
    const int acb  = (tid & 1) * 8;
    const float* pa = s_p0[arow];
    const float* pb = (MODE == 0) ? nullptr : s_p1[arow];

    for (int kk = 0; kk < K; kk += BKF) {
        #pragma unroll
        for (int j = 0; j < 8; ++j) {
            int gk = kk + acb + j;
            float v = 0.f;
            if (gk < K) {
                if (MODE == 0)      v = pa[gk];
                else if (MODE == 1) {
                    float a1 = pb[gk];
                    if (RELU_A1) a1 = fmaxf(a1, 0.f);
                    v = pa[gk] - a1;
                }
                else                v = (gk < AF) ? pa[gk] : pb[gk - AF];
            }
            As[arow][acb + j] = f2tf(v);
        }
        {
            int bk = tid >> 4;
            int nb = (tid & 15) * 8;
            int gk = kk + bk;
            bool kok = gk < K;
            const float* src = W + (size_t)(kok ? gk : 0) * N;
            #pragma unroll
            for (int j = 0; j < 8; ++j) {
                int gc = colBase + nb + j;
                float v = (kok && gc < N) ? src[gc] : 0.f;
                Bs[nb + j][bk] = f2tf(v);
            }
        }
        __syncthreads();
        #pragma unroll
        for (int ks = 0; ks < BKF; ks += 8) {
            uint32_t af[4][4], bf[4][2];
            #pragma unroll
            for (int mi = 0; mi < 4; ++mi) {
                int r = wm * 64 + mi * 16 + g;
                af[mi][0] = As[r][ks + tg];
                af[mi][1] = As[r + 8][ks + tg];
                af[mi][2] = As[r][ks + tg + 4];
                af[mi][3] = As[r + 8][ks + tg + 4];
            }
            #pragma unroll
            for (int ni = 0; ni < 4; ++ni) {
                int c = wn * 32 + ni * 8 + g;
                bf[ni][0] = Bs[c][ks + tg];
                bf[ni][1] = Bs[c][ks + tg + 4];
            }
            #pragma unroll
            for (int mi = 0; mi < 4; ++mi)
                #pragma unroll
                for (int ni = 0; ni < 4; ++ni)
                    mma8(acc[mi][ni], af[mi], bf[ni]);
        }
        __syncthreads();
    }

    #pragma unroll
    for (int mi = 0; mi < 4; ++mi) {
        int r0 = rowBase + wm * 64 + mi * 16 + g;
        #pragma unroll
        for (int ni = 0; ni < 4; ++ni) {
            int c0 = colBase + wn * 32 + ni * 8 + 2 * tg;
            if (c0 >= N) continue;
            #pragma unroll
            for (int hh = 0; hh < 2; ++hh) {
                int rr = r0 + hh * 8;
                if (rr >= M) continue;
                size_t o = (size_t)rr * N + c0;
                float v0 = acc[mi][ni][hh*2], v1 = acc[mi][ni][hh*2+1];
                if (MODE == 0) {
                    out0[o] = v0; out0[o+1] = v1;
                } else if (MODE == 1) {
                    out0[o]   = fmaxf(aux[o]   + v0, 0.f);
                    out0[o+1] = fmaxf(aux[o+1] + v1, 0.f);
                } else {
                    out0[o]   = fmaxf(v0 + aux[c0],   0.f);
                    out0[o+1] = fmaxf(v1 + aux[c0+1], 0.f);
                }
            }
        }
    }
#endif
}

// ---- Gather: amsg[a] = sum_nb ra(msg[a2b[a][nb]]) ; ra = relu if RELU ----
template<int RELU>
__global__ void gather_atoms_kernel(const float* __restrict__ msg, const int* __restrict__ a2b,
                                    float* __restrict__ amsg, int n_atoms, int max_nb)
{
    int idx = blockIdx.x * blockDim.x + threadIdx.x;
    int total = n_atoms * H4_DIM;
    if (idx >= total) return;
    int atom = idx / H4_DIM;
    int h4   = idx - atom * H4_DIM;
    float4 s = make_float4(0.f, 0.f, 0.f, 0.f);
    for (int nb = 0; nb < max_nb; ++nb) {
        int b = __ldg(&a2b[(size_t)atom * max_nb + nb]);
        float4 v = *((const float4*)(msg + (size_t)b * H_DIM) + h4);
        if (RELU) {
            v.x = fmaxf(v.x, 0.f); v.y = fmaxf(v.y, 0.f);
            v.z = fmaxf(v.z, 0.f); v.w = fmaxf(v.w, 0.f);
        }
        s.x += v.x; s.y += v.y; s.z += v.z; s.w += v.w;
    }
    ((float4*)amsg)[idx] = s;
}

// ---- Segment mean over sorted mol ids ----
__global__ void segmean_kernel(const float* __restrict__ ahid, const int* __restrict__ atom_mol,
                               float* __restrict__ out, int n_atoms, int Hh)
{
    const int m = blockIdx.x;
    __shared__ int s_bounds[2];
    if (threadIdx.x == 0) {
        int lo = 0, hi = n_atoms;
        while (lo < hi) { int mid = (lo + hi) >> 1; if (atom_mol[mid] < m) lo = mid + 1; else hi = mid; }
        s_bounds[0] = lo;
        hi = n_atoms;
        while (lo < hi) { int mid = (lo + hi) >> 1; if (atom_mol[mid] < m + 1) lo = mid + 1; else hi = mid; }
        s_bounds[1] = lo;
    }
    __syncthreads();
    const int start = s_bounds[0], end = s_bounds[1];
    const float inv = (end > start) ? 1.f / (float)(end - start) : 0.f;
    for (int h = threadIdx.x; h < Hh; h += blockDim.x) {
        float s = 0.f;
        for (int a = start; a < end; ++a) s += ahid[(size_t)a * Hh + h];
        out[(size_t)m * Hh + h] = s * inv;
    }
}

// ---------------- Launch ----------------
extern "C" void kernel_launch(void* const* d_in, const int* in_sizes, int n_in,
                              void* d_out, int out_size)
{
    const float* f_atoms = (const float*)d_in[0];
    const float* f_bonds = (const float*)d_in[1];
    const float* W_i     = (const float*)d_in[2];
    const float* W_h     = (const float*)d_in[3];
    const float* W_o     = (const float*)d_in[4];
    const float* b_o     = (const float*)d_in[5];
    const int*   a2b     = (const int*)d_in[6];
    const int*   b2a     = (const int*)d_in[7];
    const int*   b2revb  = (const int*)d_in[8];
    const int*   atom_mol= (const int*)d_in[9];

    const int H       = in_sizes[5];             // 300
    const int n_bonds = in_sizes[7];             // 200000
    const int n_atoms = in_sizes[9];             // 100000
    const int BF      = in_sizes[1] / n_bonds;   // 147
    const int AF      = in_sizes[0] / n_atoms;   // 133
    const int max_nb  = in_sizes[6] / n_atoms;   // 6
    const int n_mols  = out_size / H;            // 4000

    float* inp  = nullptr; cudaGetSymbolAddress((void**)&inp,  g_inp);
    float* msgA = nullptr; cudaGetSymbolAddress((void**)&msgA, g_msgA);
    float* msgB = nullptr; cudaGetSymbolAddress((void**)&msgB, g_msgB);
    float* amsg = nullptr; cudaGetSymbolAddress((void**)&amsg, g_amsg);
    float* ahid = nullptr; cudaGetSymbolAddress((void**)&ahid, g_ahid);
    uint32_t* pWi = nullptr; cudaGetSymbolAddress((void**)&pWi, g_packWi);
    uint32_t* pWh = nullptr; cudaGetSymbolAddress((void**)&pWh, g_packWh);
    uint32_t* pWo = nullptr; cudaGetSymbolAddress((void**)&pWo, g_packWo);

    dim3 blk(NTHR);
    dim3 grid_b((H + BN - 1) / BN, (n_bonds + BM - 1) / BM);   // (3, 1563)
    dim3 grid_a((H + BN - 1) / BN, (n_atoms + BM - 1) / BM);   // (3, 782)

    const int cbN   = (H + BN - 1) / BN;           // 3
    const int ncWi  = (BF + KC - 1) / KC;          // 5
    const int ncWh  = (H + KC - 1) / KC;           // 10
    const int ncWo  = (AF + H + KC - 1) / KC;      // 14

    const int thr = 256;
    int gatherBlocks = (n_atoms * H4_DIM + thr - 1) / thr;

    // launches 1-3: pack weights into swizzled tf32 tiles (tiny)
    pack_W_kernel<<<cbN * ncWi, thr>>>(W_i, pWi, BF, H, ncWi);
    pack_W_kernel<<<cbN * ncWh, thr>>>(W_h, pWh, H, H, ncWh);
    pack_W_kernel<<<cbN * ncWo, thr>>>(W_o, pWo, AF + H, H, ncWo);

    // launch 4: inp = f_bonds @ W_i   (relu fused into consumers)
    gemm_tc5<0,0><<<grid_b, blk>>>(f_bonds, nullptr, nullptr, nullptr, W_i, pWi, nullptr,
                                   inp, n_bonds, BF, H, 0);

    // launches 5-6: depth 1   (launch 6 = gemm_h<1,1> -> profiled by ncu -s 5 -c 1)
    gather_atoms_kernel<1><<<gatherBlocks, thr>>>(inp, a2b, amsg, n_atoms, max_nb);
    gemm_tc5<1,1><<<grid_b, blk>>>(amsg, inp, b2a, b2revb, W_h, pWh, inp,
                                   msgB, n_bonds, H, H, 0);

    // launches 7-8: depth 2
    gather_atoms_kernel<0><<<gatherBlocks, thr>>>(msgB, a2b, amsg, n_atoms, max_nb);
    gemm_tc5<1,0><<<grid_b, blk>>>(amsg, msgB, b2a, b2revb, W_h, pWh, inp,
                                   msgA, n_bonds, H, H, 0);

    // launch 9: final atom aggregation
    gather_atoms_kernel<0><<<gatherBlocks, thr>>>(msgA, a2b, amsg, n_atoms, max_nb);

    // launch 10: readout
    gemm_tc5<2,0><<<grid_a, blk>>>(f_atoms, amsg, nullptr, nullptr, W_o, pWo, b_o,
                                   ahid, n_atoms, AF + H, H, AF);

    // launch 11: per-molecule mean
    segmean_kernel<<<n_mols, 256>>>(ahid, atom_mol, (float*)d_out, n_atoms, H);
}

// round 14
// speedup vs baseline: 1.0312x; 1.0312x over previous
#include <cuda_runtime.h>
#include <cstdint>

// ---------------- Problem-size constants (fixed instance) ----------------
#define N_ATOMS_MAX  100000
#define N_BONDS_MAX  200000
#define H_DIM        300
#define H4_DIM       75

#define BM 128
#define BN 128
#define KC 32            // K-chunk: 32 tf32 = 128B rows (SW128)
#define NTHR 256
#define TILE_U32 (BN * KC)       // 4096 u32 = 16KB per packed tile
#define TILE_BYTES (TILE_U32 * 4)

#define MAX_CB 3             // col blocks for N=300
#define NC_WI  5             // ceil(147/32)
#define NC_WH  10            // ceil(300/32)
#define NC_WO  14            // ceil(433/32)

// ---------------- Device scratch (static, allocation-free) ----------------
__device__ float g_inp [(size_t)N_BONDS_MAX * H_DIM];
__device__ float g_msgA[(size_t)N_BONDS_MAX * H_DIM];
__device__ float g_msgB[(size_t)N_BONDS_MAX * H_DIM];
__device__ float g_amsg[(size_t)N_ATOMS_MAX * H_DIM];
__device__ float g_ahid[(size_t)N_ATOMS_MAX * H_DIM];
__device__ __align__(1024) uint32_t g_packWi[(size_t)MAX_CB * NC_WI * TILE_U32];
__device__ __align__(1024) uint32_t g_packWh[(size_t)MAX_CB * NC_WH * TILE_U32];
__device__ __align__(1024) uint32_t g_packWo[(size_t)MAX_CB * NC_WO * TILE_U32];

// Arch-feature gate: tcgen05 exists only in arch-specific (sm_103a) passes.
#if defined(__CUDA_ARCH_FEAT_SM103_ALL) || defined(__CUDA_ARCH_FEAT_SM100_ALL) || defined(__CUDA_ARCH_SPECIFIC__)
#define USE_TC5 1
#else
#define USE_TC5 0
#endif

// ---------------- common helpers ----------------
__device__ __forceinline__ uint32_t f2tf(float f) {
    uint32_t u;
    asm("cvt.rna.tf32.f32 %0, %1;" : "=r"(u) : "f"(f));
    return u;
}
__device__ __forceinline__ uint32_t smem_u32(const void* p) {
    uint32_t a;
    asm("{ .reg .u64 t; cvta.to.shared.u64 t, %1; cvt.u32.u64 %0, t; }" : "=r"(a) : "l"(p));
    return a;
}
__device__ __forceinline__ uint32_t sw128(uint32_t off) { return off ^ ((off >> 3) & 0x70); }

#if USE_TC5
#define TMEM_COLS 128
// idesc: bit4 dtype=F32 | atype TF32=2 @7 | btype TF32=2 @10 | (N/8)@17 | (M/16)@24
#define MMA_IDESC ((1u<<4) | (2u<<7) | (2u<<10) | ((BN/8u)<<17) | ((BM/16u)<<24))

__device__ __forceinline__ bool elect_one() {
    uint32_t p;
    asm volatile("{ .reg .pred P; elect.sync _|P, 0xFFFFFFFF; selp.b32 %0, 1, 0, P; }" : "=r"(p));
    return p != 0;
}
__device__ __forceinline__ uint64_t make_desc_sw128(uint32_t addr) {
    return (uint64_t)((addr >> 4) & 0x3FFF)
         | ((uint64_t)1  << 16) | ((uint64_t)64 << 32)
         | ((uint64_t)1  << 46) | ((uint64_t)2  << 61);
}
__device__ __forceinline__ void tmem_alloc(uint32_t smem_dst, uint32_t ncols) {
    asm volatile("tcgen05.alloc.cta_group::1.sync.aligned.shared::cta.b32 [%0], %1;"
                 :: "r"(smem_dst), "r"(ncols) : "memory");
}
__device__ __forceinline__ void tmem_relinquish() {
    asm volatile("tcgen05.relinquish_alloc_permit.cta_group::1.sync.aligned;");
}
__device__ __forceinline__ void tmem_dealloc(uint32_t tmem, uint32_t ncols) {
    asm volatile("tcgen05.dealloc.cta_group::1.sync.aligned.b32 %0, %1;" :: "r"(tmem), "r"(ncols));
}
__device__ __forceinline__ void mbar_init(uint32_t mb, uint32_t cnt) {
    asm volatile("mbarrier.init.shared.b64 [%0], %1;" :: "r"(mb), "r"(cnt) : "memory");
}
__device__ __forceinline__ void mbar_expect_tx(uint32_t mb, uint32_t bytes) {
    asm volatile("mbarrier.arrive.expect_tx.shared.b64 _, [%0], %1;"
                 :: "r"(mb), "r"(bytes) : "memory");
}
__device__ __forceinline__ void bulk_copy_g2s(uint32_t dst_smem, const void* src_gmem,
                                              uint32_t bytes, uint32_t mb) {
    asm volatile("cp.async.bulk.shared::cta.global.mbarrier::complete_tx::bytes "
                 "[%0], [%1], %2, [%3];"
                 :: "r"(dst_smem), "l"(src_gmem), "r"(bytes), "r"(mb) : "memory");
}
__device__ __forceinline__ void mbar_wait(uint32_t mb, uint32_t parity) {
    asm volatile(
        "{\n\t.reg .pred P;\n\t"
        "WL_%=:\n\t"
        "mbarrier.try_wait.parity.acquire.cta.shared::cta.b64 P, [%0], %1, 0x989680;\n\t"
        "@!P bra WL_%=;\n\t}"
        :: "r"(mb), "r"(parity) : "memory");
}
__device__ __forceinline__ void mma_tf32_ss(uint32_t d, uint64_t a, uint64_t b,
                                            uint32_t idesc, uint32_t en) {
    asm volatile(
        "{\n\t.reg .pred p;\n\tsetp.ne.u32 p, %4, 0;\n\t"
        "tcgen05.mma.cta_group::1.kind::tf32 [%0], %1, %2, %3, {%5, %5, %5, %5}, p;\n\t}"
        :: "r"(d), "l"(a), "l"(b), "r"(idesc), "r"(en), "r"(0u) : "memory");
}
__device__ __forceinline__ void mma_commit(uint32_t mb) {
    asm volatile("tcgen05.commit.cta_group::1.mbarrier::arrive::one.shared::cluster.b64 [%0];"
                 :: "r"(mb) : "memory");
}
__device__ __forceinline__ void ldtm_x32(uint32_t* r, uint32_t tmem) {
    asm volatile(
        "tcgen05.ld.sync.aligned.32x32b.x32.b32 "
        "{%0,%1,%2,%3,%4,%5,%6,%7,%8,%9,%10,%11,%12,%13,%14,%15,"
        "%16,%17,%18,%19,%20,%21,%22,%23,%24,%25,%26,%27,%28,%29,%30,%31}, [%32];"
        : "=r"(r[0]), "=r"(r[1]), "=r"(r[2]), "=r"(r[3]), "=r"(r[4]), "=r"(r[5]), "=r"(r[6]), "=r"(r[7]),
          "=r"(r[8]), "=r"(r[9]), "=r"(r[10]), "=r"(r[11]), "=r"(r[12]), "=r"(r[13]), "=r"(r[14]), "=r"(r[15]),
          "=r"(r[16]), "=r"(r[17]), "=r"(r[18]), "=r"(r[19]), "=r"(r[20]), "=r"(r[21]), "=r"(r[22]), "=r"(r[23]),
          "=r"(r[24]), "=r"(r[25]), "=r"(r[26]), "=r"(r[27]), "=r"(r[28]), "=r"(r[29]), "=r"(r[30]), "=r"(r[31])
        : "r"(tmem));
}
__device__ __forceinline__ void tmem_wait_ld() {
    asm volatile("tcgen05.wait::ld.sync.aligned;" ::: "memory");
}
__device__ __forceinline__ void tc5_fence_after() {
    asm volatile("tcgen05.fence::after_thread_sync;" ::: "memory");
}
__device__ __forceinline__ void tc5_fence_before() {
    asm volatile("tcgen05.fence::before_thread_sync;" ::: "memory");
}
__device__ __forceinline__ void fence_proxy_async_cta() {
    asm volatile("fence.proxy.async.shared::cta;" ::: "memory");
}
#endif // USE_TC5

// ---------------- mma.sync fallback helpers ----------------
#define BKF 16
#define SKF 20
__device__ __forceinline__ void mma8(float* c, const uint32_t* a, const uint32_t* b) {
    asm volatile(
        "mma.sync.aligned.m16n8k8.row.col.f32.tf32.tf32.f32 "
        "{%0,%1,%2,%3}, {%4,%5,%6,%7}, {%8,%9}, {%0,%1,%2,%3};\n"
        : "+f"(c[0]), "+f"(c[1]), "+f"(c[2]), "+f"(c[3])
        : "r"(a[0]), "r"(a[1]), "r"(a[2]), "r"(a[3]), "r"(b[0]), "r"(b[1]));
}

// ---- Pack W[K][N] into swizzled tf32 tiles: dst[cb*NC + ci][sw128 layout] ----
__global__ void pack_W_kernel(const float* __restrict__ W, uint32_t* __restrict__ dst,
                              int K, int N, int NC)
{
    const int tile = blockIdx.x;          // cb * NC + ci
    const int cb = tile / NC, ci = tile - cb * NC;
    const int colBase = cb * BN, kk = ci * KC;
    uint32_t* out = dst + (size_t)tile * TILE_U32;
    for (int i = threadIdx.x; i < TILE_U32; i += blockDim.x) {
        const int n = i >> 5, k = i & 31;
        const int gk = kk + k, gc = colBase + n;
        float v = (gk < K && gc < N) ? W[(size_t)gk * N + gc] : 0.f;
        out[sw128((uint32_t)(n << 7) + (uint32_t)(k << 2)) >> 2] = f2tf(v);
    }
}

// ---------------- Unified GEMM ----------------
// MODE 0: out0 = A0 @ W
// MODE 1: out0 = relu(aux + (A0[b2a[r]] - ra1(A1[b2revb[r]])) @ W)  ra1 = relu if RELU_A1
// MODE 2: out0 = relu([A0 | A1] @ W + aux(bias))
// Wp = pre-packed W tiles (tcgen05 path); W = raw weights (fallback path).
template<int MODE, int RELU_A1>
__global__ __launch_bounds__(NTHR, 4)
void gemm_tc5(const float* __restrict__ A0, const float* __restrict__ A1,
              const int* __restrict__ b2a, const int* __restrict__ b2revb,
              const float* __restrict__ W, const uint32_t* __restrict__ Wp,
              const float* __restrict__ aux, float* __restrict__ out0,
              int M, int K, int N, int AF)
{
    const int tid  = threadIdx.x;
    const int lane = tid & 31;
    const int wid  = tid >> 5;
    const int rowBase = blockIdx.y * BM;
    const int colBase = blockIdx.x * BN;

    __shared__ const float* s_p0[BM];
    __shared__ const float* s_p1[BM];
    if (tid < BM) {
        int gr = rowBase + tid;
        if (gr >= M) gr = M - 1;
        if (MODE == 0) {
            s_p0[tid] = A0 + (size_t)gr * K;
        } else if (MODE == 1) {
            s_p0[tid] = A0 + (size_t)b2a[gr] * K;
            s_p1[tid] = A1 + (size_t)b2revb[gr] * K;
        } else {
            s_p0[tid] = A0 + (size_t)gr * AF;
            s_p1[tid] = A1 + (size_t)gr * (K - AF);
        }
    }

#if USE_TC5
    // ====== tcgen05 tf32: reg-prefetched A + TMA bulk-copied pre-packed B ======
    __shared__ alignas(1024) uint32_t sA[BM * KC];   // 16 KB
    __shared__ alignas(1024) uint32_t sB[BN * KC];   // 16 KB
    __shared__ uint32_t s_tmem;
    __shared__ alignas(8) uint64_t s_mbar_mma;
    __shared__ alignas(8) uint64_t s_mbar_tma;

    if (wid == 0) {
        tmem_alloc(smem_u32(&s_tmem), TMEM_COLS);
        tmem_relinquish();
    }
    if (tid == 0) {
        mbar_init(smem_u32(&s_mbar_mma), 1);
        mbar_init(smem_u32(&s_mbar_tma), 1);
    }
    __syncthreads();

    const uint32_t tmem = s_tmem;
    const uint32_t mbM  = smem_u32(&s_mbar_mma);
    const uint32_t mbT  = smem_u32(&s_mbar_tma);
    const uint32_t sB_addr = smem_u32(sB);
    const uint64_t adesc = make_desc_sw128(smem_u32(sA));
    const uint64_t bdesc = make_desc_sw128(sB_addr);

    uint32_t phM = 0, phT = 0;
    const int NC = (K + KC - 1) / KC;
    const uint32_t* wp = Wp + (size_t)blockIdx.x * NC * TILE_U32;

    // precomputed conflict-free swizzled store index base (proof: off[7:9] = wid)
    const uint32_t sa_lane = (uint32_t)(lane ^ (wid << 2));

    // ---- A prefetch: 16 regs/thread, rows r = p*8 + wid, col = kk + lane ----
    float ra[16];
    {
        const int gk = lane;
        const bool kok = gk < K;
        #pragma unroll
        for (int p = 0; p < 16; ++p) {
            const int r = (p << 3) + wid;
            float v = 0.f;
            if (kok) {
                if (MODE == 0)      v = s_p0[r][gk];
                else if (MODE == 1) {
                    float a1 = s_p1[r][gk];
                    if (RELU_A1) a1 = fmaxf(a1, 0.f);
                    v = s_p0[r][gk] - a1;
                }
                else                v = (gk < AF) ? s_p0[r][gk] : s_p1[r][gk - AF];
            }
            ra[p] = v;
        }
    }

    for (int ci = 0; ci < NC; ++ci) {
        if (ci > 0) { mbar_wait(mbM, phM); phM ^= 1u; }   // sA/sB free

        // ---- issue async bulk copy of pre-packed B tile ----
        if (wid == 0 && elect_one()) {
            mbar_expect_tx(mbT, TILE_BYTES);
            bulk_copy_g2s(sB_addr, wp + (size_t)ci * TILE_U32, TILE_BYTES, mbT);
        }

        // ---- write prefetched A regs -> smem (tf32 via cvt.rna) ----
        #pragma unroll
        for (int p = 0; p < 16; ++p) {
            const int r = (p << 3) + wid;
            sA[((uint32_t)r << 5) + sa_lane] = f2tf(ra[p]);
        }

        // ---- issue next A-chunk gathered loads NOW (overlaps TMA wait + MMA) ----
        if (ci + 1 < NC) {
            const int gk = (ci + 1) * KC + lane;
            const bool kok = gk < K;
            #pragma unroll
            for (int p = 0; p < 16; ++p) {
                const int r = (p << 3) + wid;
                float v = 0.f;
                if (kok) {
                    if (MODE == 0)      v = s_p0[r][gk];
                    else if (MODE == 1) {
                        float a1 = s_p1[r][gk];
                        if (RELU_A1) a1 = fmaxf(a1, 0.f);
                        v = s_p0[r][gk] - a1;
                    }
                    else                v = (gk < AF) ? s_p0[r][gk] : s_p1[r][gk - AF];
                }
                ra[p] = v;
            }
        }

        // ---- wait for B tile, then sync A visibility ----
        mbar_wait(mbT, phT); phT ^= 1u;
        __syncthreads();

        if (wid == 0) {
            fence_proxy_async_cta();
            if (elect_one()) {
                #pragma unroll
                for (int ks = 0; ks < 4; ++ks) {
                    const uint32_t en = (ci > 0 || ks > 0) ? 1u : 0u;
                    mma_tf32_ss(tmem, adesc + (uint64_t)(ks * 2), bdesc + (uint64_t)(ks * 2),
                                MMA_IDESC, en);
                }
                mma_commit(mbM);
            }
        }
    }

    mbar_wait(mbM, phM);

    // ---- epilogue: warp w -> rows (w&3)*32+lane ; cols (w>>2)*64..+63 ----
    tc5_fence_after();
    const int gr = rowBase + (wid & 3) * 32 + lane;
    const bool rok = gr < M;
    const int cb0 = (wid >> 2) * 2;

    #pragma unroll
    for (int bb = 0; bb < 2; ++bb) {
        const int b = cb0 + bb;
        uint32_t d[32];
        ldtm_x32(d, tmem + (uint32_t)(b * 32));
        tmem_wait_ld();
        if (rok) {
            const int cbase = colBase + b * 32;
            #pragma unroll
            for (int j = 0; j < 32; j += 4) {
                const int c = cbase + j;
                if (c + 3 < N) {
                    const size_t o = (size_t)gr * N + c;
                    float4 v = make_float4(__uint_as_float(d[j]), __uint_as_float(d[j+1]),
                                           __uint_as_float(d[j+2]), __uint_as_float(d[j+3]));
                    if (MODE == 0) {
                        *(float4*)(out0 + o) = v;
                    } else if (MODE == 1) {
                        float4 i4 = *(const float4*)(aux + o);
                        *(float4*)(out0 + o) = make_float4(
                            fmaxf(i4.x+v.x,0.f), fmaxf(i4.y+v.y,0.f),
                            fmaxf(i4.z+v.z,0.f), fmaxf(i4.w+v.w,0.f));
                    } else {
                        *(float4*)(out0 + o) = make_float4(
                            fmaxf(v.x+aux[c],0.f),   fmaxf(v.y+aux[c+1],0.f),
                            fmaxf(v.z+aux[c+2],0.f), fmaxf(v.w+aux[c+3],0.f));
                    }
                } else {
                    #pragma unroll
                    for (int q = 0; q < 4; ++q) {
                        const int cc = c + q;
                        if (cc >= N) break;
                        const size_t o = (size_t)gr * N + cc;
                        const float v = __uint_as_float(d[j + q]);
                        if (MODE == 0)      { out0[o] = v; }
                        else if (MODE == 1) { out0[o] = fmaxf(aux[o] + v, 0.f); }
                        else                { out0[o] = fmaxf(v + aux[cc], 0.f); }
                    }
                }
            }
        }
    }
    tc5_fence_before();
    __syncthreads();
    if (wid == 0) tmem_dealloc(tmem, TMEM_COLS);

#else
    // ================= mma.sync tf32 fallback (8 warps) =================
    __shared__ uint32_t As[BM][SKF];
    __shared__ uint32_t Bs[BN][SKF];
    __syncthreads();

    const int wm = wid >> 2, wn = wid & 3;
    const int g = lane >> 2, tg = lane & 3;

    float acc[4][4][4] = {};

    const int arow = tid >> 1;
    const int acb  = (tid & 1) * 8;
    const float* pa = s_p0[arow];
    const float* pb = (MODE == 0) ? nullptr : s_p1[arow];

    for (int kk = 0; kk < K; kk += BKF) {
        #pragma unroll
        for (int j = 0; j < 8; ++j) {
            int gk = kk + acb + j;
            float v = 0.f;
            if (gk < K) {
                if (MODE == 0)      v = pa[gk];
                else if (MODE == 1) {
                    float a1 = pb[gk];
                    if (RELU_A1) a1 = fmaxf(a1, 0.f);
                    v = pa[gk] - a1;
                }
                else                v = (gk < AF) ? pa[gk] : pb[gk - AF];
            }
            As[arow][acb + j] = f2tf(v);
        }
        {
            int bk = tid >> 4;
            int nb = (tid & 15) * 8;
            int gk = kk + bk;
            bool kok = gk < K;
            const float* src = W + (size_t)(kok ? gk : 0) * N;
            #pragma unroll
            for (int j = 0; j < 8; ++j) {
                int gc = colBase + nb + j;
                float v = (kok && gc < N) ? src[gc] : 0.f;
                Bs[nb + j][bk] = f2tf(v);
            }
        }
        __syncthreads();
        #pragma unroll
        for (int ks = 0; ks < BKF; ks += 8) {
            uint32_t af[4][4], bf[4][2];
            #pragma unroll
            for (int mi = 0; mi < 4; ++mi) {
                int r = wm * 64 + mi * 16 + g;
                af[mi][0] = As[r][ks + tg];
                af[mi][1] = As[r + 8][ks + tg];
                af[mi][2] = As[r][ks + tg + 4];
                af[mi][3] = As[r + 8][ks + tg + 4];
            }
            #pragma unroll
            for (int ni = 0; ni < 4; ++ni) {
                int c = wn * 32 + ni * 8 + g;
                bf[ni][0] = Bs[c][ks + tg];
                bf[ni][1] = Bs[c][ks + tg + 4];
            }
            #pragma unroll
            for (int mi = 0; mi < 4; ++mi)
                #pragma unroll
                for (int ni = 0; ni < 4; ++ni)
                    mma8(acc[mi][ni], af[mi], bf[ni]);
        }
        __syncthreads();
    }

    #pragma unroll
    for (int mi = 0; mi < 4; ++mi) {
        int r0 = rowBase + wm * 64 + mi * 16 + g;
        #pragma unroll
        for (int ni = 0; ni < 4; ++ni) {
            int c0 = colBase + wn * 32 + ni * 8 + 2 * tg;
            if (c0 >= N) continue;
            #pragma unroll
            for (int hh = 0; hh < 2; ++hh) {
                int rr = r0 + hh * 8;
                if (rr >= M) continue;
                size_t o = (size_t)rr * N + c0;
                float v0 = acc[mi][ni][hh*2], v1 = acc[mi][ni][hh*2+1];
                if (MODE == 0) {
                    out0[o] = v0; out0[o+1] = v1;
                } else if (MODE == 1) {
                    out0[o]   = fmaxf(aux[o]   + v0, 0.f);
                    out0[o+1] = fmaxf(aux[o+1] + v1, 0.f);
                } else {
                    out0[o]   = fmaxf(v0 + aux[c0],   0.f);
                    out0[o+1] = fmaxf(v1 + aux[c0+1], 0.f);
                }
            }
        }
    }
#endif
}

// ---- Gather: amsg[a] = sum_nb ra(msg[a2b[a][nb]]) ; ra = relu if RELU ----
template<int RELU>
__global__ void gather_atoms_kernel(const float* __restrict__ msg, const int* __restrict__ a2b,
                                    float* __restrict__ amsg, int n_atoms, int max_nb)
{
    int idx = blockIdx.x * blockDim.x + threadIdx.x;
    int total = n_atoms * H4_DIM;
    if (idx >= total) return;
    int atom = idx / H4_DIM;
    int h4   = idx - atom * H4_DIM;
    float4 s = make_float4(0.f, 0.f, 0.f, 0.f);
    for (int nb = 0; nb < max_nb; ++nb) {
        int b = __ldg(&a2b[(size_t)atom * max_nb + nb]);
        float4 v = *((const float4*)(msg + (size_t)b * H_DIM) + h4);
        if (RELU) {
            v.x = fmaxf(v.x, 0.f); v.y = fmaxf(v.y, 0.f);
            v.z = fmaxf(v.z, 0.f); v.w = fmaxf(v.w, 0.f);
        }
        s.x += v.x; s.y += v.y; s.z += v.z; s.w += v.w;
    }
    ((float4*)amsg)[idx] = s;
}

// ---- Segment mean over sorted mol ids ----
__global__ void segmean_kernel(const float* __restrict__ ahid, const int* __restrict__ atom_mol,
                               float* __restrict__ out, int n_atoms, int Hh)
{
    const int m = blockIdx.x;
    __shared__ int s_bounds[2];
    if (threadIdx.x == 0) {
        int lo = 0, hi = n_atoms;
        while (lo < hi) { int mid = (lo + hi) >> 1; if (atom_mol[mid] < m) lo = mid + 1; else hi = mid; }
        s_bounds[0] = lo;
        hi = n_atoms;
        while (lo < hi) { int mid = (lo + hi) >> 1; if (atom_mol[mid] < m + 1) lo = mid + 1; else hi = mid; }
        s_bounds[1] = lo;
    }
    __syncthreads();
    const int start = s_bounds[0], end = s_bounds[1];
    const float inv = (end > start) ? 1.f / (float)(end - start) : 0.f;
    for (int h = threadIdx.x; h < Hh; h += blockDim.x) {
        float s = 0.f;
        for (int a = start; a < end; ++a) s += ahid[(size_t)a * Hh + h];
        out[(size_t)m * Hh + h] = s * inv;
    }
}

// ---------------- Launch ----------------
extern "C" void kernel_launch(void* const* d_in, const int* in_sizes, int n_in,
                              void* d_out, int out_size)
{
    const float* f_atoms = (const float*)d_in[0];
    const float* f_bonds = (const float*)d_in[1];
    const float* W_i     = (const float*)d_in[2];
    const float* W_h     = (const float*)d_in[3];
    const float* W_o     = (const float*)d_in[4];
    const float* b_o     = (const float*)d_in[5];
    const int*   a2b     = (const int*)d_in[6];
    const int*   b2a     = (const int*)d_in[7];
    const int*   b2revb  = (const int*)d_in[8];
    const int*   atom_mol= (const int*)d_in[9];

    const int H       = in_sizes[5];             // 300
    const int n_bonds = in_sizes[7];             // 200000
    const int n_atoms = in_sizes[9];             // 100000
    const int BF      = in_sizes[1] / n_bonds;   // 147
    const int AF      = in_sizes[0] / n_atoms;   // 133
    const int max_nb  = in_sizes[6] / n_atoms;   // 6
    const int n_mols  = out_size / H;            // 4000

    float* inp  = nullptr; cudaGetSymbolAddress((void**)&inp,  g_inp);
    float* msgA = nullptr; cudaGetSymbolAddress((void**)&msgA, g_msgA);
    float* msgB = nullptr; cudaGetSymbolAddress((void**)&msgB, g_msgB);
    float* amsg = nullptr; cudaGetSymbolAddress((void**)&amsg, g_amsg);
    float* ahid = nullptr; cudaGetSymbolAddress((void**)&ahid, g_ahid);
    uint32_t* pWi = nullptr; cudaGetSymbolAddress((void**)&pWi, g_packWi);
    uint32_t* pWh = nullptr; cudaGetSymbolAddress((void**)&pWh, g_packWh);
    uint32_t* pWo = nullptr; cudaGetSymbolAddress((void**)&pWo, g_packWo);

    // Hint max shared-memory carveout for the GEMM kernels (occupancy).
    static bool s_attr_done = false;
    if (!s_attr_done) {
        cudaFuncSetAttribute(gemm_tc5<0,0>, cudaFuncAttributePreferredSharedMemoryCarveout, 100);
        cudaFuncSetAttribute(gemm_tc5<1,1>, cudaFuncAttributePreferredSharedMemoryCarveout, 100);
        cudaFuncSetAttribute(gemm_tc5<1,0>, cudaFuncAttributePreferredSharedMemoryCarveout, 100);
        cudaFuncSetAttribute(gemm_tc5<2,0>, cudaFuncAttributePreferredSharedMemoryCarveout, 100);
        s_attr_done = true;
    }

    dim3 blk(NTHR);
    dim3 grid_b((H + BN - 1) / BN, (n_bonds + BM - 1) / BM);   // (3, 1563)
    dim3 grid_a((H + BN - 1) / BN, (n_atoms + BM - 1) / BM);   // (3, 782)

    const int cbN   = (H + BN - 1) / BN;           // 3
    const int ncWi  = (BF + KC - 1) / KC;          // 5
    const int ncWh  = (H + KC - 1) / KC;           // 10
    const int ncWo  = (AF + H + KC - 1) / KC;      // 14

    const int thr = 256;
    int gatherBlocks = (n_atoms * H4_DIM + thr - 1) / thr;

    // launches 1-3: pack weights into swizzled tf32 tiles (tiny)
    pack_W_kernel<<<cbN * ncWi, thr>>>(W_i, pWi, BF, H, ncWi);
    pack_W_kernel<<<cbN * ncWh, thr>>>(W_h, pWh, H, H, ncWh);
    pack_W_kernel<<<cbN * ncWo, thr>>>(W_o, pWo, AF + H, H, ncWo);

    // launch 4: inp = f_bonds @ W_i   (relu fused into consumers)
    gemm_tc5<0,0><<<grid_b, blk>>>(f_bonds, nullptr, nullptr, nullptr, W_i, pWi, nullptr,
                                   inp, n_bonds, BF, H, 0);

    // launches 5-6: depth 1   (launch 6 = gemm_h<1,1> -> profiled by ncu -s 5 -c 1)
    gather_atoms_kernel<1><<<gatherBlocks, thr>>>(inp, a2b, amsg, n_atoms, max_nb);
    gemm_tc5<1,1><<<grid_b, blk>>>(amsg, inp, b2a, b2revb, W_h, pWh, inp,
                                   msgB, n_bonds, H, H, 0);

    // launches 7-8: depth 2
    gather_atoms_kernel<0><<<gatherBlocks, thr>>>(msgB, a2b, amsg, n_atoms, max_nb);
    gemm_tc5<1,0><<<grid_b, blk>>>(amsg, msgB, b2a, b2revb, W_h, pWh, inp,
                                   msgA, n_bonds, H, H, 0);

    // launch 9: final atom aggregation
    gather_atoms_kernel<0><<<gatherBlocks, thr>>>(msgA, a2b, amsg, n_atoms, max_nb);

    // launch 10: readout
    gemm_tc5<2,0><<<grid_a, blk>>>(f_atoms, amsg, nullptr, nullptr, W_o, pWo, b_o,
                                   ahid, n_atoms, AF + H, H, AF);

    // launch 11: per-molecule mean
    segmean_kernel<<<n_mols, 256>>>(ahid, atom_mol, (float*)d_out, n_atoms, H);
}

// round 15
// speedup vs baseline: 1.5178x; 1.4719x over previous
#include <cuda_runtime.h>
#include <cstdint>

// ---------------- Problem-size constants (fixed instance) ----------------
#define N_ATOMS_MAX  100000
#define N_BONDS_MAX  200000
#define H_DIM        300
#define H4_DIM       75

#define BM 128
#define BN 128
#define KC 32            // K-chunk: 32 tf32 = 128B rows (SW128)
#define NTHR 256
#define TILE_U32 (BN * KC)       // 4096 u32 = 16KB per packed tile
#define TILE_BYTES (TILE_U32 * 4)

#define MAX_CB 3             // col blocks for N=300
#define NC_WI  5             // ceil(147/32)
#define NC_WH  10            // ceil(300/32)
#define NC_WO  14            // ceil(433/32)

// ---------------- Device scratch (static, allocation-free) ----------------
__device__ float g_inp [(size_t)N_BONDS_MAX * H_DIM];
__device__ float g_msgA[(size_t)N_BONDS_MAX * H_DIM];
__device__ float g_msgB[(size_t)N_BONDS_MAX * H_DIM];
__device__ float g_amsg[(size_t)N_ATOMS_MAX * H_DIM];
__device__ float g_ahid[(size_t)N_ATOMS_MAX * H_DIM];
__device__ __align__(1024) uint32_t g_packWi[(size_t)MAX_CB * NC_WI * TILE_U32];
__device__ __align__(1024) uint32_t g_packWh[(size_t)MAX_CB * NC_WH * TILE_U32];
__device__ __align__(1024) uint32_t g_packWo[(size_t)MAX_CB * NC_WO * TILE_U32];

// Arch-feature gate: tcgen05 exists only in arch-specific (sm_103a) passes.
#if defined(__CUDA_ARCH_FEAT_SM103_ALL) || defined(__CUDA_ARCH_FEAT_SM100_ALL) || defined(__CUDA_ARCH_SPECIFIC__)
#define USE_TC5 1
#else
#define USE_TC5 0
#endif

// ---------------- common helpers ----------------
__device__ __forceinline__ uint32_t f2tf(float f) {
    uint32_t u;
    asm("cvt.rna.tf32.f32 %0, %1;" : "=r"(u) : "f"(f));
    return u;
}
__device__ __forceinline__ uint32_t smem_u32(const void* p) {
    uint32_t a;
    asm("{ .reg .u64 t; cvta.to.shared.u64 t, %1; cvt.u32.u64 %0, t; }" : "=r"(a) : "l"(p));
    return a;
}
__device__ __forceinline__ uint32_t sw128(uint32_t off) { return off ^ ((off >> 3) & 0x70); }

#if USE_TC5
#define TMEM_COLS 128
// idesc: bit4 dtype=F32 | atype TF32=2 @7 | btype TF32=2 @10 | (N/8)@17 | (M/16)@24
#define MMA_IDESC ((1u<<4) | (2u<<7) | (2u<<10) | ((BN/8u)<<17) | ((BM/16u)<<24))

__device__ __forceinline__ bool elect_one() {
    uint32_t p;
    asm volatile("{ .reg .pred P; elect.sync _|P, 0xFFFFFFFF; selp.b32 %0, 1, 0, P; }" : "=r"(p));
    return p != 0;
}
__device__ __forceinline__ uint64_t make_desc_sw128(uint32_t addr) {
    return (uint64_t)((addr >> 4) & 0x3FFF)
         | ((uint64_t)1  << 16) | ((uint64_t)64 << 32)
         | ((uint64_t)1  << 46) | ((uint64_t)2  << 61);
}
__device__ __forceinline__ void tmem_alloc(uint32_t smem_dst, uint32_t ncols) {
    asm volatile("tcgen05.alloc.cta_group::1.sync.aligned.shared::cta.b32 [%0], %1;"
                 :: "r"(smem_dst), "r"(ncols) : "memory");
}
__device__ __forceinline__ void tmem_relinquish() {
    asm volatile("tcgen05.relinquish_alloc_permit.cta_group::1.sync.aligned;");
}
__device__ __forceinline__ void tmem_dealloc(uint32_t tmem, uint32_t ncols) {
    asm volatile("tcgen05.dealloc.cta_group::1.sync.aligned.b32 %0, %1;" :: "r"(tmem), "r"(ncols));
}
__device__ __forceinline__ void mbar_init(uint32_t mb, uint32_t cnt) {
    asm volatile("mbarrier.init.shared.b64 [%0], %1;" :: "r"(mb), "r"(cnt) : "memory");
}
__device__ __forceinline__ void mbar_expect_tx(uint32_t mb, uint32_t bytes) {
    asm volatile("mbarrier.arrive.expect_tx.shared.b64 _, [%0], %1;"
                 :: "r"(mb), "r"(bytes) : "memory");
}
__device__ __forceinline__ void bulk_copy_g2s(uint32_t dst_smem, const void* src_gmem,
                                              uint32_t bytes, uint32_t mb) {
    asm volatile("cp.async.bulk.shared::cta.global.mbarrier::complete_tx::bytes "
                 "[%0], [%1], %2, [%3];"
                 :: "r"(dst_smem), "l"(src_gmem), "r"(bytes), "r"(mb) : "memory");
}
__device__ __forceinline__ void mbar_wait(uint32_t mb, uint32_t parity) {
    asm volatile(
        "{\n\t.reg .pred P;\n\t"
        "WL_%=:\n\t"
        "mbarrier.try_wait.parity.acquire.cta.shared::cta.b64 P, [%0], %1, 0x989680;\n\t"
        "@!P bra WL_%=;\n\t}"
        :: "r"(mb), "r"(parity) : "memory");
}
__device__ __forceinline__ void mma_tf32_ss(uint32_t d, uint64_t a, uint64_t b,
                                            uint32_t idesc, uint32_t en) {
    asm volatile(
        "{\n\t.reg .pred p;\n\tsetp.ne.u32 p, %4, 0;\n\t"
        "tcgen05.mma.cta_group::1.kind::tf32 [%0], %1, %2, %3, {%5, %5, %5, %5}, p;\n\t}"
        :: "r"(d), "l"(a), "l"(b), "r"(idesc), "r"(en), "r"(0u) : "memory");
}
__device__ __forceinline__ void mma_commit(uint32_t mb) {
    asm volatile("tcgen05.commit.cta_group::1.mbarrier::arrive::one.shared::cluster.b64 [%0];"
                 :: "r"(mb) : "memory");
}
__device__ __forceinline__ void ldtm_x32(uint32_t* r, uint32_t tmem) {
    asm volatile(
        "tcgen05.ld.sync.aligned.32x32b.x32.b32 "
        "{%0,%1,%2,%3,%4,%5,%6,%7,%8,%9,%10,%11,%12,%13,%14,%15,"
        "%16,%17,%18,%19,%20,%21,%22,%23,%24,%25,%26,%27,%28,%29,%30,%31}, [%32];"
        : "=r"(r[0]), "=r"(r[1]), "=r"(r[2]), "=r"(r[3]), "=r"(r[4]), "=r"(r[5]), "=r"(r[6]), "=r"(r[7]),
          "=r"(r[8]), "=r"(r[9]), "=r"(r[10]), "=r"(r[11]), "=r"(r[12]), "=r"(r[13]), "=r"(r[14]), "=r"(r[15]),
          "=r"(r[16]), "=r"(r[17]), "=r"(r[18]), "=r"(r[19]), "=r"(r[20]), "=r"(r[21]), "=r"(r[22]), "=r"(r[23]),
          "=r"(r[24]), "=r"(r[25]), "=r"(r[26]), "=r"(r[27]), "=r"(r[28]), "=r"(r[29]), "=r"(r[30]), "=r"(r[31])
        : "r"(tmem));
}
__device__ __forceinline__ void tmem_wait_ld() {
    asm volatile("tcgen05.wait::ld.sync.aligned;" ::: "memory");
}
__device__ __forceinline__ void tc5_fence_after() {
    asm volatile("tcgen05.fence::after_thread_sync;" ::: "memory");
}
__device__ __forceinline__ void tc5_fence_before() {
    asm volatile("tcgen05.fence::before_thread_sync;" ::: "memory");
}
__device__ __forceinline__ void fence_proxy_async_cta() {
    asm volatile("fence.proxy.async.shared::cta;" ::: "memory");
}
#endif // USE_TC5

// ---------------- mma.sync fallback helpers ----------------
#define BKF 16
#define SKF 20
__device__ __forceinline__ void mma8(float* c, const uint32_t* a, const uint32_t* b) {
    asm volatile(
        "mma.sync.aligned.m16n8k8.row.col.f32.tf32.tf32.f32 "
        "{%0,%1,%2,%3}, {%4,%5,%6,%7}, {%8,%9}, {%0,%1,%2,%3};\n"
        : "+f"(c[0]), "+f"(c[1]), "+f"(c[2]), "+f"(c[3])
        : "r"(a[0]), "r"(a[1]), "r"(a[2]), "r"(a[3]), "r"(b[0]), "r"(b[1]));
}

// ---- Pack W[K][N] into swizzled tf32 tiles: dst[cb*NC + ci][sw128 layout] ----
__global__ void pack_W_kernel(const float* __restrict__ W, uint32_t* __restrict__ dst,
                              int K, int N, int NC)
{
    const int tile = blockIdx.x;          // cb * NC + ci
    const int cb = tile / NC, ci = tile - cb * NC;
    const int colBase = cb * BN, kk = ci * KC;
    uint32_t* out = dst + (size_t)tile * TILE_U32;
    for (int i = threadIdx.x; i < TILE_U32; i += blockDim.x) {
        const int n = i >> 5, k = i & 31;
        const int gk = kk + k, gc = colBase + n;
        float v = (gk < K && gc < N) ? W[(size_t)gk * N + gc] : 0.f;
        out[sw128((uint32_t)(n << 7) + (uint32_t)(k << 2)) >> 2] = f2tf(v);
    }
}

// ---------------- Unified GEMM ----------------
// MODE 0: out0 = A0 @ W
// MODE 1: out0 = relu(aux + (A0[b2a[r]] - ra1(A1[b2revb[r]])) @ W)  ra1 = relu if RELU_A1
// MODE 2: out0 = relu([A0 | A1] @ W + aux(bias))
// Wp = pre-packed W tiles (tcgen05 path); W = raw weights (fallback path).
template<int MODE, int RELU_A1>
__global__ __launch_bounds__(NTHR, 4)
void gemm_tc5(const float* __restrict__ A0, const float* __restrict__ A1,
              const int* __restrict__ b2a, const int* __restrict__ b2revb,
              const float* __restrict__ W, const uint32_t* __restrict__ Wp,
              const float* __restrict__ aux, float* __restrict__ out0,
              int M, int K, int N, int AF)
{
    const int tid  = threadIdx.x;
    const int lane = tid & 31;
    const int wid  = tid >> 5;
    const int rowBase = blockIdx.y * BM;
    const int colBase = blockIdx.x * BN;

    __shared__ const float* s_p0[BM];
    __shared__ const float* s_p1[BM];
    if (tid < BM) {
        int gr = rowBase + tid;
        if (gr >= M) gr = M - 1;
        if (MODE == 0) {
            s_p0[tid] = A0 + (size_t)gr * K;
        } else if (MODE == 1) {
            s_p0[tid] = A0 + (size_t)b2a[gr] * K;
            s_p1[tid] = A1 + (size_t)b2revb[gr] * K;
        } else {
            s_p0[tid] = A0 + (size_t)gr * AF;
            s_p1[tid] = A1 + (size_t)gr * (K - AF);
        }
    }

#if USE_TC5
    // ====== tcgen05 tf32: reg-prefetched A + TMA bulk-copied pre-packed B ======
    __shared__ alignas(1024) uint32_t sA[BM * KC];   // 16 KB
    __shared__ alignas(1024) uint32_t sB[BN * KC];   // 16 KB
    __shared__ uint32_t s_tmem;
    __shared__ alignas(8) uint64_t s_mbar_mma;
    __shared__ alignas(8) uint64_t s_mbar_tma;

    if (wid == 0) {
        tmem_alloc(smem_u32(&s_tmem), TMEM_COLS);
        tmem_relinquish();
    }
    if (tid == 0) {
        mbar_init(smem_u32(&s_mbar_mma), 1);
        mbar_init(smem_u32(&s_mbar_tma), 1);
    }
    __syncthreads();

    const uint32_t tmem = s_tmem;
    const uint32_t mbM  = smem_u32(&s_mbar_mma);
    const uint32_t mbT  = smem_u32(&s_mbar_tma);
    const uint32_t sB_addr = smem_u32(sB);
    const uint64_t adesc = make_desc_sw128(smem_u32(sA));
    const uint64_t bdesc = make_desc_sw128(sB_addr);

    uint32_t phM = 0, phT = 0;
    const int NC = (K + KC - 1) / KC;
    const uint32_t* wp = Wp + (size_t)blockIdx.x * NC * TILE_U32;

    // precomputed conflict-free swizzled store index base (proof: off[7:9] = wid)
    const uint32_t sa_lane = (uint32_t)(lane ^ (wid << 2));

    // ---- A prefetch: 16 regs/thread, rows r = p*8 + wid, col = kk + lane ----
    float ra[16];
    {
        const int gk = lane;
        const bool kok = gk < K;
        #pragma unroll
        for (int p = 0; p < 16; ++p) {
            const int r = (p << 3) + wid;
            float v = 0.f;
            if (kok) {
                if (MODE == 0)      v = s_p0[r][gk];
                else if (MODE == 1) {
                    float a1 = s_p1[r][gk];
                    if (RELU_A1) a1 = fmaxf(a1, 0.f);
                    v = s_p0[r][gk] - a1;
                }
                else                v = (gk < AF) ? s_p0[r][gk] : s_p1[r][gk - AF];
            }
            ra[p] = v;
        }
    }

    for (int ci = 0; ci < NC; ++ci) {
        if (ci > 0) { mbar_wait(mbM, phM); phM ^= 1u; }   // sA/sB free

        // ---- issue async bulk copy of pre-packed B tile ----
        if (wid == 0 && elect_one()) {
            mbar_expect_tx(mbT, TILE_BYTES);
            bulk_copy_g2s(sB_addr, wp + (size_t)ci * TILE_U32, TILE_BYTES, mbT);
        }

        // ---- write prefetched A regs -> smem (tf32 via cvt.rna) ----
        #pragma unroll
        for (int p = 0; p < 16; ++p) {
            const int r = (p << 3) + wid;
            sA[((uint32_t)r << 5) + sa_lane] = f2tf(ra[p]);
        }

        // ---- issue next A-chunk gathered loads NOW (overlaps TMA wait + MMA) ----
        if (ci + 1 < NC) {
            const int gk = (ci + 1) * KC + lane;
            const bool kok = gk < K;
            #pragma unroll
            for (int p = 0; p < 16; ++p) {
                const int r = (p << 3) + wid;
                float v = 0.f;
                if (kok) {
                    if (MODE == 0)      v = s_p0[r][gk];
                    else if (MODE == 1) {
                        float a1 = s_p1[r][gk];
                        if (RELU_A1) a1 = fmaxf(a1, 0.f);
                        v = s_p0[r][gk] - a1;
                    }
                    else                v = (gk < AF) ? s_p0[r][gk] : s_p1[r][gk - AF];
                }
                ra[p] = v;
            }
        }

        // ---- wait for B tile, then sync A visibility ----
        mbar_wait(mbT, phT); phT ^= 1u;
        __syncthreads();

        if (wid == 0) {
            fence_proxy_async_cta();
            if (elect_one()) {
                #pragma unroll
                for (int ks = 0; ks < 4; ++ks) {
                    const uint32_t en = (ci > 0 || ks > 0) ? 1u : 0u;
                    mma_tf32_ss(tmem, adesc + (uint64_t)(ks * 2), bdesc + (uint64_t)(ks * 2),
                                MMA_IDESC, en);
                }
                mma_commit(mbM);
            }
        }
    }

    mbar_wait(mbM, phM);

    // ---- epilogue: warp w -> rows (w&3)*32+lane ; cols (w>>2)*64..+63 ----
    tc5_fence_after();
    const int gr = rowBase + (wid & 3) * 32 + lane;
    const bool rok = gr < M;
    const int cb0 = (wid >> 2) * 2;

    #pragma unroll
    for (int bb = 0; bb < 2; ++bb) {
        const int b = cb0 + bb;
        uint32_t d[32];
        ldtm_x32(d, tmem + (uint32_t)(b * 32));
        tmem_wait_ld();
        if (rok) {
            const int cbase = colBase + b * 32;
            #pragma unroll
            for (int j = 0; j < 32; j += 4) {
                const int c = cbase + j;
                if (c + 3 < N) {
                    const size_t o = (size_t)gr * N + c;
                    float4 v = make_float4(__uint_as_float(d[j]), __uint_as_float(d[j+1]),
                                           __uint_as_float(d[j+2]), __uint_as_float(d[j+3]));
                    if (MODE == 0) {
                        *(float4*)(out0 + o) = v;
                    } else if (MODE == 1) {
                        float4 i4 = *(const float4*)(aux + o);
                        *(float4*)(out0 + o) = make_float4(
                            fmaxf(i4.x+v.x,0.f), fmaxf(i4.y+v.y,0.f),
                            fmaxf(i4.z+v.z,0.f), fmaxf(i4.w+v.w,0.f));
                    } else {
                        *(float4*)(out0 + o) = make_float4(
                            fmaxf(v.x+aux[c],0.f),   fmaxf(v.y+aux[c+1],0.f),
                            fmaxf(v.z+aux[c+2],0.f), fmaxf(v.w+aux[c+3],0.f));
                    }
                } else {
                    #pragma unroll
                    for (int q = 0; q < 4; ++q) {
                        const int cc = c + q;
                        if (cc >= N) break;
                        const size_t o = (size_t)gr * N + cc;
                        const float v = __uint_as_float(d[j + q]);
                        if (MODE == 0)      { out0[o] = v; }
                        else if (MODE == 1) { out0[o] = fmaxf(aux[o] + v, 0.f); }
                        else                { out0[o] = fmaxf(v + aux[cc], 0.f); }
                    }
                }
            }
        }
    }
    tc5_fence_before();
    __syncthreads();
    if (wid == 0) tmem_dealloc(tmem, TMEM_COLS);

#else
    // ================= mma.sync tf32 fallback (8 warps) =================
    __shared__ uint32_t As[BM][SKF];
    __shared__ uint32_t Bs[BN][SKF];
    __syncthreads();

    const int wm = wid >> 2, wn = wid & 3;
    const int g = lane >> 2, tg = lane & 3;

    float acc[4][4][4] = {};

    const int arow = tid >> 1;
    const int acb  = (tid & 1) * 8;
    const float* pa = s_p0[arow];
    const float* pb = (MODE == 0) ? nullptr : s_p1[arow];

    for (int kk = 0; kk < K; kk += BKF) {
        #pragma unroll
        for (int j = 0; j < 8; ++j) {
            int gk = kk + acb + j;
            float v = 0.f;
            if (gk < K) {
                if (MODE == 0)      v = pa[gk];
                else if (MODE == 1) {
                    float a1 = pb[gk];
                    if (RELU_A1) a1 = fmaxf(a1, 0.f);
                    v = pa[gk] - a1;
                }
                else                v = (gk < AF) ? pa[gk] : pb[gk - AF];
            }
            As[arow][acb + j] = f2tf(v);
        }
        {
            int bk = tid >> 4;
            int nb = (tid & 15) * 8;
            int gk = kk + bk;
            bool kok = gk < K;
            const float* src = W + (size_t)(kok ? gk : 0) * N;
            #pragma unroll
            for (int j = 0; j < 8; ++j) {
                int gc = colBase + nb + j;
                float v = (kok && gc < N) ? src[gc] : 0.f;
                Bs[nb + j][bk] = f2tf(v);
            }
        }
        __syncthreads();
        #pragma unroll
        for (int ks = 0; ks < BKF; ks += 8) {
            uint32_t af[4][4], bf[4][2];
            #pragma unroll
            for (int mi = 0; mi < 4; ++mi) {
                int r = wm * 64 + mi * 16 + g;
                af[mi][0] = As[r][ks + tg];
                af[mi][1] = As[r + 8][ks + tg];
                af[mi][2] = As[r][ks + tg + 4];
                af[mi][3] = As[r + 8][ks + tg + 4];
            }
            #pragma unroll
            for (int ni = 0; ni < 4; ++ni) {
                int c = wn * 32 + ni * 8 + g;
                bf[ni][0] = Bs[c][ks + tg];
                bf[ni][1] = Bs[c][ks + tg + 4];
            }
            #pragma unroll
            for (int mi = 0; mi < 4; ++mi)
                #pragma unroll
                for (int ni = 0; ni < 4; ++ni)
                    mma8(acc[mi][ni], af[mi], bf[ni]);
        }
        __syncthreads();
    }

    #pragma unroll
    for (int mi = 0; mi < 4; ++mi) {
        int r0 = rowBase + wm * 64 + mi * 16 + g;
        #pragma unroll
        for (int ni = 0; ni < 4; ++ni) {
            int c0 = colBase + wn * 32 + ni * 8 + 2 * tg;
            if (c0 >= N) continue;
            #pragma unroll
            for (int hh = 0; hh < 2; ++hh) {
                int rr = r0 + hh * 8;
                if (rr >= M) continue;
                size_t o = (size_t)rr * N + c0;
                float v0 = acc[mi][ni][hh*2], v1 = acc[mi][ni][hh*2+1];
                if (MODE == 0) {
                    out0[o] = v0; out0[o+1] = v1;
                } else if (MODE == 1) {
                    out0[o]   = fmaxf(aux[o]   + v0, 0.f);
                    out0[o+1] = fmaxf(aux[o+1] + v1, 0.f);
                } else {
                    out0[o]   = fmaxf(v0 + aux[c0],   0.f);
                    out0[o+1] = fmaxf(v1 + aux[c0+1], 0.f);
                }
            }
        }
    }
#endif
}

// ---- Gather: amsg[a] = sum_nb ra(msg[a2b[a][nb]]) ; ra = relu if RELU ----
template<int RELU>
__global__ void gather_atoms_kernel(const float* __restrict__ msg, const int* __restrict__ a2b,
                                    float* __restrict__ amsg, int n_atoms, int max_nb)
{
    int idx = blockIdx.x * blockDim.x + threadIdx.x;
    int total = n_atoms * H4_DIM;
    if (idx >= total) return;
    int atom = idx / H4_DIM;
    int h4   = idx - atom * H4_DIM;
    float4 s = make_float4(0.f, 0.f, 0.f, 0.f);
    for (int nb = 0; nb < max_nb; ++nb) {
        int b = __ldg(&a2b[(size_t)atom * max_nb + nb]);
        float4 v = *((const float4*)(msg + (size_t)b * H_DIM) + h4);
        if (RELU) {
            v.x = fmaxf(v.x, 0.f); v.y = fmaxf(v.y, 0.f);
            v.z = fmaxf(v.z, 0.f); v.w = fmaxf(v.w, 0.f);
        }
        s.x += v.x; s.y += v.y; s.z += v.z; s.w += v.w;
    }
    ((float4*)amsg)[idx] = s;
}

// ---- Segment mean over sorted mol ids ----
__global__ void segmean_kernel(const float* __restrict__ ahid, const int* __restrict__ atom_mol,
                               float* __restrict__ out, int n_atoms, int Hh)
{
    const int m = blockIdx.x;
    __shared__ int s_bounds[2];
    if (threadIdx.x == 0) {
        int lo = 0, hi = n_atoms;
        while (lo < hi) { int mid = (lo + hi) >> 1; if (atom_mol[mid] < m) lo = mid + 1; else hi = mid; }
        s_bounds[0] = lo;
        hi = n_atoms;
        while (lo < hi) { int mid = (lo + hi) >> 1; if (atom_mol[mid] < m + 1) lo = mid + 1; else hi = mid; }
        s_bounds[1] = lo;
    }
    __syncthreads();
    const int start = s_bounds[0], end = s_bounds[1];
    const float inv = (end > start) ? 1.f / (float)(end - start) : 0.f;
    for (int h = threadIdx.x; h < Hh; h += blockDim.x) {
        float s = 0.f;
        for (int a = start; a < end; ++a) s += ahid[(size_t)a * Hh + h];
        out[(size_t)m * Hh + h] = s * inv;
    }
}

// ---------------- Launch ----------------
extern "C" void kernel_launch(void* const* d_in, const int* in_sizes, int n_in,
                              void* d_out, int out_size)
{
    const float* f_atoms = (const float*)d_in[0];
    const float* f_bonds = (const float*)d_in[1];
    const float* W_i     = (const float*)d_in[2];
    const float* W_h     = (const float*)d_in[3];
    const float* W_o     = (const float*)d_in[4];
    const float* b_o     = (const float*)d_in[5];
    const int*   a2b     = (const int*)d_in[6];
    const int*   b2a     = (const int*)d_in[7];
    const int*   b2revb  = (const int*)d_in[8];
    const int*   atom_mol= (const int*)d_in[9];

    const int H       = in_sizes[5];             // 300
    const int n_bonds = in_sizes[7];             // 200000
    const int n_atoms = in_sizes[9];             // 100000
    const int BF      = in_sizes[1] / n_bonds;   // 147
    const int AF      = in_sizes[0] / n_atoms;   // 133
    const int max_nb  = in_sizes[6] / n_atoms;   // 6
    const int n_mols  = out_size / H;            // 4000

    float* inp  = nullptr; cudaGetSymbolAddress((void**)&inp,  g_inp);
    float* msgA = nullptr; cudaGetSymbolAddress((void**)&msgA, g_msgA);
    float* msgB = nullptr; cudaGetSymbolAddress((void**)&msgB, g_msgB);
    float* amsg = nullptr; cudaGetSymbolAddress((void**)&amsg, g_amsg);
    float* ahid = nullptr; cudaGetSymbolAddress((void**)&ahid, g_ahid);
    uint32_t* pWi = nullptr; cudaGetSymbolAddress((void**)&pWi, g_packWi);
    uint32_t* pWh = nullptr; cudaGetSymbolAddress((void**)&pWh, g_packWh);
    uint32_t* pWo = nullptr; cudaGetSymbolAddress((void**)&pWo, g_packWo);

    dim3 blk(NTHR);
    dim3 grid_b((H + BN - 1) / BN, (n_bonds + BM - 1) / BM);   // (3, 1563)
    dim3 grid_a((H + BN - 1) / BN, (n_atoms + BM - 1) / BM);   // (3, 782)

    const int cbN   = (H + BN - 1) / BN;           // 3
    const int ncWi  = (BF + KC - 1) / KC;          // 5
    const int ncWh  = (H + KC - 1) / KC;           // 10
    const int ncWo  = (AF + H + KC - 1) / KC;      // 14

    const int thr = 256;
    int gatherBlocks = (n_atoms * H4_DIM + thr - 1) / thr;

    // launches 1-3: pack weights into swizzled tf32 tiles (tiny)
    pack_W_kernel<<<cbN * ncWi, thr>>>(W_i, pWi, BF, H, ncWi);
    pack_W_kernel<<<cbN * ncWh, thr>>>(W_h, pWh, H, H, ncWh);
    pack_W_kernel<<<cbN * ncWo, thr>>>(W_o, pWo, AF + H, H, ncWo);

    // launch 4: inp = f_bonds @ W_i   (relu fused into consumers)
    gemm_tc5<0,0><<<grid_b, blk>>>(f_bonds, nullptr, nullptr, nullptr, W_i, pWi, nullptr,
                                   inp, n_bonds, BF, H, 0);

    // launches 5-6: depth 1   (launch 6 = gemm_h<1,1> -> profiled by ncu -s 5 -c 1)
    gather_atoms_kernel<1><<<gatherBlocks, thr>>>(inp, a2b, amsg, n_atoms, max_nb);
    gemm_tc5<1,1><<<grid_b, blk>>>(amsg, inp, b2a, b2revb, W_h, pWh, inp,
                                   msgB, n_bonds, H, H, 0);

    // launches 7-8: depth 2
    gather_atoms_kernel<0><<<gatherBlocks, thr>>>(msgB, a2b, amsg, n_atoms, max_nb);
    gemm_tc5<1,0><<<grid_b, blk>>>(amsg, msgB, b2a, b2revb, W_h, pWh, inp,
                                   msgA, n_bonds, H, H, 0);

    // launch 9: final atom aggregation
    gather_atoms_kernel<0><<<gatherBlocks, thr>>>(msgA, a2b, amsg, n_atoms, max_nb);

    // launch 10: readout
    gemm_tc5<2,0><<<grid_a, blk>>>(f_atoms, amsg, nullptr, nullptr, W_o, pWo, b_o,
                                   ahid, n_atoms, AF + H, H, AF);

    // launch 11: per-molecule mean
    segmean_kernel<<<n_mols, 256>>>(ahid, atom_mol, (float*)d_out, n_atoms, H);
}

// round 16
// speedup vs baseline: 1.5755x; 1.0380x over previous
#include <cuda_runtime.h>
#include <cstdint>

// ---------------- Problem-size constants (fixed instance) ----------------
#define N_ATOMS_MAX  100000
#define N_BONDS_MAX  200000
#define H_DIM        300
#define H4_DIM       75

#define BM 128
#define BN 128
#define KC 32            // K-chunk: 32 tf32 = 128B rows (SW128)
#define NTHR 256
#define TILE_U32 (BN * KC)       // 4096 u32 = 16KB per packed tile
#define TILE_BYTES (TILE_U32 * 4)

#define MAX_CB 3             // col blocks for N=300
#define NC_WI  5             // ceil(147/32)
#define NC_WH  10            // ceil(300/32)
#define NC_WO  14            // ceil(433/32)

// ---------------- Device scratch (static, allocation-free) ----------------
__device__ float g_inp [(size_t)N_BONDS_MAX * H_DIM];
__device__ float g_msgA[(size_t)N_BONDS_MAX * H_DIM];
__device__ float g_msgB[(size_t)N_BONDS_MAX * H_DIM];
__device__ float g_amsg[(size_t)N_ATOMS_MAX * H_DIM];
__device__ float g_ahid[(size_t)N_ATOMS_MAX * H_DIM];
__device__ __align__(1024) uint32_t g_packWi[(size_t)MAX_CB * NC_WI * TILE_U32];
__device__ __align__(1024) uint32_t g_packWh[(size_t)MAX_CB * NC_WH * TILE_U32];
__device__ __align__(1024) uint32_t g_packWo[(size_t)MAX_CB * NC_WO * TILE_U32];

// Arch-feature gate: tcgen05 exists only in arch-specific (sm_103a) passes.
#if defined(__CUDA_ARCH_FEAT_SM103_ALL) || defined(__CUDA_ARCH_FEAT_SM100_ALL) || defined(__CUDA_ARCH_SPECIFIC__)
#define USE_TC5 1
#else
#define USE_TC5 0
#endif

// ---------------- common helpers ----------------
__device__ __forceinline__ uint32_t f2tf(float f) {
    uint32_t u;
    asm("cvt.rna.tf32.f32 %0, %1;" : "=r"(u) : "f"(f));
    return u;
}
__device__ __forceinline__ uint32_t smem_u32(const void* p) {
    uint32_t a;
    asm("{ .reg .u64 t; cvta.to.shared.u64 t, %1; cvt.u32.u64 %0, t; }" : "=r"(a) : "l"(p));
    return a;
}
__device__ __forceinline__ uint32_t sw128(uint32_t off) { return off ^ ((off >> 3) & 0x70); }

#if USE_TC5
#define TMEM_COLS 128
// idesc: bit4 dtype=F32 | atype TF32=2 @7 | btype TF32=2 @10 | (N/8)@17 | (M/16)@24
#define MMA_IDESC ((1u<<4) | (2u<<7) | (2u<<10) | ((BN/8u)<<17) | ((BM/16u)<<24))

__device__ __forceinline__ bool elect_one() {
    uint32_t p;
    asm volatile("{ .reg .pred P; elect.sync _|P, 0xFFFFFFFF; selp.b32 %0, 1, 0, P; }" : "=r"(p));
    return p != 0;
}
__device__ __forceinline__ uint64_t make_desc_sw128(uint32_t addr) {
    return (uint64_t)((addr >> 4) & 0x3FFF)
         | ((uint64_t)1  << 16) | ((uint64_t)64 << 32)
         | ((uint64_t)1  << 46) | ((uint64_t)2  << 61);
}
__device__ __forceinline__ void tmem_alloc(uint32_t smem_dst, uint32_t ncols) {
    asm volatile("tcgen05.alloc.cta_group::1.sync.aligned.shared::cta.b32 [%0], %1;"
                 :: "r"(smem_dst), "r"(ncols) : "memory");
}
__device__ __forceinline__ void tmem_relinquish() {
    asm volatile("tcgen05.relinquish_alloc_permit.cta_group::1.sync.aligned;");
}
__device__ __forceinline__ void tmem_dealloc(uint32_t tmem, uint32_t ncols) {
    asm volatile("tcgen05.dealloc.cta_group::1.sync.aligned.b32 %0, %1;" :: "r"(tmem), "r"(ncols));
}
__device__ __forceinline__ void mbar_init(uint32_t mb, uint32_t cnt) {
    asm volatile("mbarrier.init.shared.b64 [%0], %1;" :: "r"(mb), "r"(cnt) : "memory");
}
__device__ __forceinline__ void mbar_expect_tx(uint32_t mb, uint32_t bytes) {
    asm volatile("mbarrier.arrive.expect_tx.shared.b64 _, [%0], %1;"
                 :: "r"(mb), "r"(bytes) : "memory");
}
__device__ __forceinline__ void bulk_copy_g2s(uint32_t dst_smem, const void* src_gmem,
                                              uint32_t bytes, uint32_t mb) {
    asm volatile("cp.async.bulk.shared::cta.global.mbarrier::complete_tx::bytes "
                 "[%0], [%1], %2, [%3];"
                 :: "r"(dst_smem), "l"(src_gmem), "r"(bytes), "r"(mb) : "memory");
}
__device__ __forceinline__ void mbar_wait(uint32_t mb, uint32_t parity) {
    asm volatile(
        "{\n\t.reg .pred P;\n\t"
        "WL_%=:\n\t"
        "mbarrier.try_wait.parity.acquire.cta.shared::cta.b64 P, [%0], %1, 0x989680;\n\t"
        "@!P bra WL_%=;\n\t}"
        :: "r"(mb), "r"(parity) : "memory");
}
__device__ __forceinline__ void mma_tf32_ss(uint32_t d, uint64_t a, uint64_t b,
                                            uint32_t idesc, uint32_t en) {
    asm volatile(
        "{\n\t.reg .pred p;\n\tsetp.ne.u32 p, %4, 0;\n\t"
        "tcgen05.mma.cta_group::1.kind::tf32 [%0], %1, %2, %3, {%5, %5, %5, %5}, p;\n\t}"
        :: "r"(d), "l"(a), "l"(b), "r"(idesc), "r"(en), "r"(0u) : "memory");
}
__device__ __forceinline__ void mma_commit(uint32_t mb) {
    asm volatile("tcgen05.commit.cta_group::1.mbarrier::arrive::one.shared::cluster.b64 [%0];"
                 :: "r"(mb) : "memory");
}
__device__ __forceinline__ void ldtm_x32(uint32_t* r, uint32_t tmem) {
    asm volatile(
        "tcgen05.ld.sync.aligned.32x32b.x32.b32 "
        "{%0,%1,%2,%3,%4,%5,%6,%7,%8,%9,%10,%11,%12,%13,%14,%15,"
        "%16,%17,%18,%19,%20,%21,%22,%23,%24,%25,%26,%27,%28,%29,%30,%31}, [%32];"
        : "=r"(r[0]), "=r"(r[1]), "=r"(r[2]), "=r"(r[3]), "=r"(r[4]), "=r"(r[5]), "=r"(r[6]), "=r"(r[7]),
          "=r"(r[8]), "=r"(r[9]), "=r"(r[10]), "=r"(r[11]), "=r"(r[12]), "=r"(r[13]), "=r"(r[14]), "=r"(r[15]),
          "=r"(r[16]), "=r"(r[17]), "=r"(r[18]), "=r"(r[19]), "=r"(r[20]), "=r"(r[21]), "=r"(r[22]), "=r"(r[23]),
          "=r"(r[24]), "=r"(r[25]), "=r"(r[26]), "=r"(r[27]), "=r"(r[28]), "=r"(r[29]), "=r"(r[30]), "=r"(r[31])
        : "r"(tmem));
}
__device__ __forceinline__ void tmem_wait_ld() {
    asm volatile("tcgen05.wait::ld.sync.aligned;" ::: "memory");
}
__device__ __forceinline__ void tc5_fence_after() {
    asm volatile("tcgen05.fence::after_thread_sync;" ::: "memory");
}
__device__ __forceinline__ void tc5_fence_before() {
    asm volatile("tcgen05.fence::before_thread_sync;" ::: "memory");
}
__device__ __forceinline__ void fence_proxy_async_cta() {
    asm volatile("fence.proxy.async.shared::cta;" ::: "memory");
}
#endif // USE_TC5

// ---------------- mma.sync fallback helpers ----------------
#define BKF 16
#define SKF 20
__device__ __forceinline__ void mma8(float* c, const uint32_t* a, const uint32_t* b) {
    asm volatile(
        "mma.sync.aligned.m16n8k8.row.col.f32.tf32.tf32.f32 "
        "{%0,%1,%2,%3}, {%4,%5,%6,%7}, {%8,%9}, {%0,%1,%2,%3};\n"
        : "+f"(c[0]), "+f"(c[1]), "+f"(c[2]), "+f"(c[3])
        : "r"(a[0]), "r"(a[1]), "r"(a[2]), "r"(a[3]), "r"(b[0]), "r"(b[1]));
}

// ---- Pack W[K][N] into swizzled tf32 tiles: dst[cb*NC + ci][sw128 layout] ----
__global__ void pack_W_kernel(const float* __restrict__ W, uint32_t* __restrict__ dst,
                              int K, int N, int NC)
{
    const int tile = blockIdx.x;          // cb * NC + ci
    const int cb = tile / NC, ci = tile - cb * NC;
    const int colBase = cb * BN, kk = ci * KC;
    uint32_t* out = dst + (size_t)tile * TILE_U32;
    for (int i = threadIdx.x; i < TILE_U32; i += blockDim.x) {
        const int n = i >> 5, k = i & 31;
        const int gk = kk + k, gc = colBase + n;
        float v = (gk < K && gc < N) ? W[(size_t)gk * N + gc] : 0.f;
        out[sw128((uint32_t)(n << 7) + (uint32_t)(k << 2)) >> 2] = f2tf(v);
    }
}

// ---------------- Unified GEMM ----------------
// MODE 0: out0 = A0 @ W
// MODE 1: out0 = relu(aux + (A0[b2a[r]] - ra1(A1[b2revb[r]])) @ W)  ra1 = relu if RELU_A1
// MODE 2: out0 = relu([A0 | A1] @ W + aux(bias))
// Wp = pre-packed W tiles (tcgen05 path); W = raw weights (fallback path).
template<int MODE, int RELU_A1>
__global__ __launch_bounds__(NTHR, 4)
void gemm_tc5(const float* __restrict__ A0, const float* __restrict__ A1,
              const int* __restrict__ b2a, const int* __restrict__ b2revb,
              const float* __restrict__ W, const uint32_t* __restrict__ Wp,
              const float* __restrict__ aux, float* __restrict__ out0,
              int M, int K, int N, int AF)
{
    const int tid  = threadIdx.x;
    const int lane = tid & 31;
    const int wid  = tid >> 5;
    const int rowBase = blockIdx.y * BM;
    const int colBase = blockIdx.x * BN;

    __shared__ const float* s_p0[BM];
    __shared__ const float* s_p1[BM];
    if (tid < BM) {
        int gr = rowBase + tid;
        if (gr >= M) gr = M - 1;
        if (MODE == 0) {
            s_p0[tid] = A0 + (size_t)gr * K;
        } else if (MODE == 1) {
            s_p0[tid] = A0 + (size_t)b2a[gr] * K;
            s_p1[tid] = A1 + (size_t)b2revb[gr] * K;
        } else {
            s_p0[tid] = A0 + (size_t)gr * AF;
            s_p1[tid] = A1 + (size_t)gr * (K - AF);
        }
    }

#if USE_TC5
    // ====== tcgen05 tf32: reg-prefetched A (two independent streams) + TMA packed B ======
    __shared__ alignas(1024) uint32_t sA[BM * KC];   // 16 KB
    __shared__ alignas(1024) uint32_t sB[BN * KC];   // 16 KB
    __shared__ uint32_t s_tmem;
    __shared__ alignas(8) uint64_t s_mbar_mma;
    __shared__ alignas(8) uint64_t s_mbar_tma;

    if (wid == 0) {
        tmem_alloc(smem_u32(&s_tmem), TMEM_COLS);
        tmem_relinquish();
    }
    if (tid == 0) {
        mbar_init(smem_u32(&s_mbar_mma), 1);
        mbar_init(smem_u32(&s_mbar_tma), 1);
    }
    __syncthreads();

    const uint32_t tmem = s_tmem;
    const uint32_t mbM  = smem_u32(&s_mbar_mma);
    const uint32_t mbT  = smem_u32(&s_mbar_tma);
    const uint32_t sB_addr = smem_u32(sB);
    const uint64_t adesc = make_desc_sw128(smem_u32(sA));
    const uint64_t bdesc = make_desc_sw128(sB_addr);

    uint32_t phM = 0, phT = 0;
    const int NC = (K + KC - 1) / KC;
    const uint32_t* wp = Wp + (size_t)blockIdx.x * NC * TILE_U32;

    // precomputed conflict-free swizzled store index base (proof: off[7:9] = wid)
    const uint32_t sa_lane = (uint32_t)(lane ^ (wid << 2));

    // ---- A prefetch: two independent register streams (max MLP) ----
    // MODE 1 keeps ra (from p0) and rb (from p1) separate; diff happens at store.
    float ra[16];
    float rb[16];   // used only by MODE 1
    {
        const int gk = lane;
        const bool kok = gk < K;
        if (MODE == 1) {
            #pragma unroll
            for (int p = 0; p < 16; ++p) {
                const int r = (p << 3) + wid;
                ra[p] = kok ? s_p0[r][gk] : 0.f;
            }
            #pragma unroll
            for (int p = 0; p < 16; ++p) {
                const int r = (p << 3) + wid;
                rb[p] = kok ? s_p1[r][gk] : 0.f;
            }
        } else {
            #pragma unroll
            for (int p = 0; p < 16; ++p) {
                const int r = (p << 3) + wid;
                float v = 0.f;
                if (kok) {
                    if (MODE == 0) v = s_p0[r][gk];
                    else           v = (gk < AF) ? s_p0[r][gk] : s_p1[r][gk - AF];
                }
                ra[p] = v;
            }
        }
    }

    for (int ci = 0; ci < NC; ++ci) {
        if (ci > 0) { mbar_wait(mbM, phM); phM ^= 1u; }   // sA/sB free

        // ---- issue async bulk copy of pre-packed B tile ----
        if (wid == 0 && elect_one()) {
            mbar_expect_tx(mbT, TILE_BYTES);
            bulk_copy_g2s(sB_addr, wp + (size_t)ci * TILE_U32, TILE_BYTES, mbT);
        }

        // ---- write prefetched A regs -> smem (diff/relu folded into store) ----
        #pragma unroll
        for (int p = 0; p < 16; ++p) {
            const int r = (p << 3) + wid;
            float v;
            if (MODE == 1) {
                float b = rb[p];
                if (RELU_A1) b = fmaxf(b, 0.f);
                v = ra[p] - b;
            } else {
                v = ra[p];
            }
            sA[((uint32_t)r << 5) + sa_lane] = f2tf(v);
        }

        // ---- issue next A-chunk gathered loads NOW (overlaps TMA wait + MMA) ----
        if (ci + 1 < NC) {
            const int gk = (ci + 1) * KC + lane;
            const bool kok = gk < K;
            if (MODE == 1) {
                #pragma unroll
                for (int p = 0; p < 16; ++p) {
                    const int r = (p << 3) + wid;
                    ra[p] = kok ? s_p0[r][gk] : 0.f;
                }
                #pragma unroll
                for (int p = 0; p < 16; ++p) {
                    const int r = (p << 3) + wid;
                    rb[p] = kok ? s_p1[r][gk] : 0.f;
                }
            } else {
                #pragma unroll
                for (int p = 0; p < 16; ++p) {
                    const int r = (p << 3) + wid;
                    float v = 0.f;
                    if (kok) {
                        if (MODE == 0) v = s_p0[r][gk];
                        else           v = (gk < AF) ? s_p0[r][gk] : s_p1[r][gk - AF];
                    }
                    ra[p] = v;
                }
            }
        }

        // ---- wait for B tile, then sync A visibility ----
        mbar_wait(mbT, phT); phT ^= 1u;
        __syncthreads();

        if (wid == 0) {
            fence_proxy_async_cta();
            if (elect_one()) {
                #pragma unroll
                for (int ks = 0; ks < 4; ++ks) {
                    const uint32_t en = (ci > 0 || ks > 0) ? 1u : 0u;
                    mma_tf32_ss(tmem, adesc + (uint64_t)(ks * 2), bdesc + (uint64_t)(ks * 2),
                                MMA_IDESC, en);
                }
                mma_commit(mbM);
            }
        }
    }

    mbar_wait(mbM, phM);

    // ---- epilogue: warp w -> rows (w&3)*32+lane ; cols (w>>2)*64..+63 ----
    tc5_fence_after();
    const int gr = rowBase + (wid & 3) * 32 + lane;
    const bool rok = gr < M;
    const int cb0 = (wid >> 2) * 2;

    #pragma unroll
    for (int bb = 0; bb < 2; ++bb) {
        const int b = cb0 + bb;
        uint32_t d[32];
        ldtm_x32(d, tmem + (uint32_t)(b * 32));
        tmem_wait_ld();
        if (rok) {
            const int cbase = colBase + b * 32;
            #pragma unroll
            for (int j = 0; j < 32; j += 4) {
                const int c = cbase + j;
                if (c + 3 < N) {
                    const size_t o = (size_t)gr * N + c;
                    float4 v = make_float4(__uint_as_float(d[j]), __uint_as_float(d[j+1]),
                                           __uint_as_float(d[j+2]), __uint_as_float(d[j+3]));
                    if (MODE == 0) {
                        *(float4*)(out0 + o) = v;
                    } else if (MODE == 1) {
                        float4 i4 = *(const float4*)(aux + o);
                        *(float4*)(out0 + o) = make_float4(
                            fmaxf(i4.x+v.x,0.f), fmaxf(i4.y+v.y,0.f),
                            fmaxf(i4.z+v.z,0.f), fmaxf(i4.w+v.w,0.f));
                    } else {
                        *(float4*)(out0 + o) = make_float4(
                            fmaxf(v.x+aux[c],0.f),   fmaxf(v.y+aux[c+1],0.f),
                            fmaxf(v.z+aux[c+2],0.f), fmaxf(v.w+aux[c+3],0.f));
                    }
                } else {
                    #pragma unroll
                    for (int q = 0; q < 4; ++q) {
                        const int cc = c + q;
                        if (cc >= N) break;
                        const size_t o = (size_t)gr * N + cc;
                        const float v = __uint_as_float(d[j + q]);
                        if (MODE == 0)      { out0[o] = v; }
                        else if (MODE == 1) { out0[o] = fmaxf(aux[o] + v, 0.f); }
                        else                { out0[o] = fmaxf(v + aux[cc], 0.f); }
                    }
                }
            }
        }
    }
    tc5_fence_before();
    __syncthreads();
    if (wid == 0) tmem_dealloc(tmem, TMEM_COLS);

#else
    // ================= mma.sync tf32 fallback (8 warps) =================
    __shared__ uint32_t As[BM][SKF];
    __shared__ uint32_t Bs[BN][SKF];
    __syncthreads();

    const int wm = wid >> 2, wn = wid & 3;
    const int g = lane >> 2, tg = lane & 3;

    float acc[4][4][4] = {};

    const int arow = tid >> 1;
    const int acb  = (tid & 1) * 8;
    const float* pa = s_p0[arow];
    const float* pb = (MODE == 0) ? nullptr : s_p1[arow];

    for (int kk = 0; kk < K; kk += BKF) {
        #pragma unroll
        for (int j = 0; j < 8; ++j) {
            int gk = kk + acb + j;
            float v = 0.f;
            if (gk < K) {
                if (MODE == 0)      v = pa[gk];
                else if (MODE == 1) {
                    float a1 = pb[gk];
                    if (RELU_A1) a1 = fmaxf(a1, 0.f);
                    v = pa[gk] - a1;
                }
                else                v = (gk < AF) ? pa[gk] : pb[gk - AF];
            }
            As[arow][acb + j] = f2tf(v);
        }
        {
            int bk = tid >> 4;
            int nb = (tid & 15) * 8;
            int gk = kk + bk;
            bool kok = gk < K;
            const float* src = W + (size_t)(kok ? gk : 0) * N;
            #pragma unroll
            for (int j = 0; j < 8; ++j) {
                int gc = colBase + nb + j;
                float v = (kok && gc < N) ? src[gc] : 0.f;
                Bs[nb + j][bk] = f2tf(v);
            }
        }
        __syncthreads();
        #pragma unroll
        for (int ks = 0; ks < BKF; ks += 8) {
            uint32_t af[4][4], bf[4][2];
            #pragma unroll
            for (int mi = 0; mi < 4; ++mi) {
                int r = wm * 64 + mi * 16 + g;
                af[mi][0] = As[r][ks + tg];
                af[mi][1] = As[r + 8][ks + tg];
                af[mi][2] = As[r][ks + tg + 4];
                af[mi][3] = As[r + 8][ks + tg + 4];
            }
            #pragma unroll
            for (int ni = 0; ni < 4; ++ni) {
                int c = wn * 32 + ni * 8 + g;
                bf[ni][0] = Bs[c][ks + tg];
                bf[ni][1] = Bs[c][ks + tg + 4];
            }
            #pragma unroll
            for (int mi = 0; mi < 4; ++mi)
                #pragma unroll
                for (int ni = 0; ni < 4; ++ni)
                    mma8(acc[mi][ni], af[mi], bf[ni]);
        }
        __syncthreads();
    }

    #pragma unroll
    for (int mi = 0; mi < 4; ++mi) {
        int r0 = rowBase + wm * 64 + mi * 16 + g;
        #pragma unroll
        for (int ni = 0; ni < 4; ++ni) {
            int c0 = colBase + wn * 32 + ni * 8 + 2 * tg;
            if (c0 >= N) continue;
            #pragma unroll
            for (int hh = 0; hh < 2; ++hh) {
                int rr = r0 + hh * 8;
                if (rr >= M) continue;
                size_t o = (size_t)rr * N + c0;
                float v0 = acc[mi][ni][hh*2], v1 = acc[mi][ni][hh*2+1];
                if (MODE == 0) {
                    out0[o] = v0; out0[o+1] = v1;
                } else if (MODE == 1) {
                    out0[o]   = fmaxf(aux[o]   + v0, 0.f);
                    out0[o+1] = fmaxf(aux[o+1] + v1, 0.f);
                } else {
                    out0[o]   = fmaxf(v0 + aux[c0],   0.f);
                    out0[o+1] = fmaxf(v1 + aux[c0+1], 0.f);
                }
            }
        }
    }
#endif
}

// ---- Gather: amsg[a] = sum_nb ra(msg[a2b[a][nb]]) ; ra = relu if RELU ----
template<int RELU>
__global__ void gather_atoms_kernel(const float* __restrict__ msg, const int* __restrict__ a2b,
                                    float* __restrict__ amsg, int n_atoms, int max_nb)
{
    int idx = blockIdx.x * blockDim.x + threadIdx.x;
    int total = n_atoms * H4_DIM;
    if (idx >= total) return;
    int atom = idx / H4_DIM;
    int h4   = idx - atom * H4_DIM;
    float4 s = make_float4(0.f, 0.f, 0.f, 0.f);
    for (int nb = 0; nb < max_nb; ++nb) {
        int b = __ldg(&a2b[(size_t)atom * max_nb + nb]);
        float4 v = *((const float4*)(msg + (size_t)b * H_DIM) + h4);
        if (RELU) {
            v.x = fmaxf(v.x, 0.f); v.y = fmaxf(v.y, 0.f);
            v.z = fmaxf(v.z, 0.f); v.w = fmaxf(v.w, 0.f);
        }
        s.x += v.x; s.y += v.y; s.z += v.z; s.w += v.w;
    }
    ((float4*)amsg)[idx] = s;
}

// ---- Segment mean over sorted mol ids ----
__global__ void segmean_kernel(const float* __restrict__ ahid, const int* __restrict__ atom_mol,
                               float* __restrict__ out, int n_atoms, int Hh)
{
    const int m = blockIdx.x;
    __shared__ int s_bounds[2];
    if (threadIdx.x == 0) {
        int lo = 0, hi = n_atoms;
        while (lo < hi) { int mid = (lo + hi) >> 1; if (atom_mol[mid] < m) lo = mid + 1; else hi = mid; }
        s_bounds[0] = lo;
        hi = n_atoms;
        while (lo < hi) { int mid = (lo + hi) >> 1; if (atom_mol[mid] < m + 1) lo = mid + 1; else hi = mid; }
        s_bounds[1] = lo;
    }
    __syncthreads();
    const int start = s_bounds[0], end = s_bounds[1];
    const float inv = (end > start) ? 1.f / (float)(end - start) : 0.f;
    for (int h = threadIdx.x; h < Hh; h += blockDim.x) {
        float s = 0.f;
        for (int a = start; a < end; ++a) s += ahid[(size_t)a * Hh + h];
        out[(size_t)m * Hh + h] = s * inv;
    }
}

// ---------------- Launch ----------------
extern "C" void kernel_launch(void* const* d_in, const int* in_sizes, int n_in,
                              void* d_out, int out_size)
{
    const float* f_atoms = (const float*)d_in[0];
    const float* f_bonds = (const float*)d_in[1];
    const float* W_i     = (const float*)d_in[2];
    const float* W_h     = (const float*)d_in[3];
    const float* W_o     = (const float*)d_in[4];
    const float* b_o     = (const float*)d_in[5];
    const int*   a2b     = (const int*)d_in[6];
    const int*   b2a     = (const int*)d_in[7];
    const int*   b2revb  = (const int*)d_in[8];
    const int*   atom_mol= (const int*)d_in[9];

    const int H       = in_sizes[5];             // 300
    const int n_bonds = in_sizes[7];             // 200000
    const int n_atoms = in_sizes[9];             // 100000
    const int BF      = in_sizes[1] / n_bonds;   // 147
    const int AF      = in_sizes[0] / n_atoms;   // 133
    const int max_nb  = in_sizes[6] / n_atoms;   // 6
    const int n_mols  = out_size / H;            // 4000

    float* inp  = nullptr; cudaGetSymbolAddress((void**)&inp,  g_inp);
    float* msgA = nullptr; cudaGetSymbolAddress((void**)&msgA, g_msgA);
    float* msgB = nullptr; cudaGetSymbolAddress((void**)&msgB, g_msgB);
    float* amsg = nullptr; cudaGetSymbolAddress((void**)&amsg, g_amsg);
    float* ahid = nullptr; cudaGetSymbolAddress((void**)&ahid, g_ahid);
    uint32_t* pWi = nullptr; cudaGetSymbolAddress((void**)&pWi, g_packWi);
    uint32_t* pWh = nullptr; cudaGetSymbolAddress((void**)&pWh, g_packWh);
    uint32_t* pWo = nullptr; cudaGetSymbolAddress((void**)&pWo, g_packWo);

    dim3 blk(NTHR);
    dim3 grid_b((H + BN - 1) / BN, (n_bonds + BM - 1) / BM);   // (3, 1563)
    dim3 grid_a((H + BN - 1) / BN, (n_atoms + BM - 1) / BM);   // (3, 782)

    const int cbN   = (H + BN - 1) / BN;           // 3
    const int ncWi  = (BF + KC - 1) / KC;          // 5
    const int ncWh  = (H + KC - 1) / KC;           // 10
    const int ncWo  = (AF + H + KC - 1) / KC;      // 14

    const int thr = 256;
    int gatherBlocks = (n_atoms * H4_DIM + thr - 1) / thr;

    // launches 1-3: pack weights into swizzled tf32 tiles (tiny)
    pack_W_kernel<<<cbN * ncWi, thr>>>(W_i, pWi, BF, H, ncWi);
    pack_W_kernel<<<cbN * ncWh, thr>>>(W_h, pWh, H, H, ncWh);
    pack_W_kernel<<<cbN * ncWo, thr>>>(W_o, pWo, AF + H, H, ncWo);

    // launch 4: inp = f_bonds @ W_i   (relu fused into consumers)
    gemm_tc5<0,0><<<grid_b, blk>>>(f_bonds, nullptr, nullptr, nullptr, W_i, pWi, nullptr,
                                   inp, n_bonds, BF, H, 0);

    // launches 5-6: depth 1   (launch 6 = gemm_h<1,1> -> profiled by ncu -s 5 -c 1)
    gather_atoms_kernel<1><<<gatherBlocks, thr>>>(inp, a2b, amsg, n_atoms, max_nb);
    gemm_tc5<1,1><<<grid_b, blk>>>(amsg, inp, b2a, b2revb, W_h, pWh, inp,
                                   msgB, n_bonds, H, H, 0);

    // launches 7-8: depth 2
    gather_atoms_kernel<0><<<gatherBlocks, thr>>>(msgB, a2b, amsg, n_atoms, max_nb);
    gemm_tc5<1,0><<<grid_b, blk>>>(amsg, msgB, b2a, b2revb, W_h, pWh, inp,
                                   msgA, n_bonds, H, H, 0);

    // launch 9: final atom aggregation
    gather_atoms_kernel<0><<<gatherBlocks, thr>>>(msgA, a2b, amsg, n_atoms, max_nb);

    // launch 10: readout
    gemm_tc5<2,0><<<grid_a, blk>>>(f_atoms, amsg, nullptr, nullptr, W_o, pWo, b_o,
                                   ahid, n_atoms, AF + H, H, AF);

    // launch 11: per-molecule mean
    segmean_kernel<<<n_mols, 256>>>(ahid, atom_mol, (float*)d_out, n_atoms, H);
}

// round 17
// speedup vs baseline: 1.9549x; 1.2408x over previous
#include <cuda_runtime.h>
#include <cuda_fp16.h>
#include <cstdint>

// ---------------- Problem-size constants (fixed instance) ----------------
#define N_ATOMS_MAX  100000
#define N_BONDS_MAX  200000
#define H_DIM        300

#define BM 128
#define BN 128
#define KC 64            // K-chunk: 64 fp16 = 128B rows (SW128)
#define KC2 32           // half2 chunks per row
#define NTHR 256
#define TILE_U32 (BN * KC2)      // 4096 u32 = 16KB per packed tile
#define TILE_BYTES (TILE_U32 * 4)

#define MAX_CB 3             // col blocks for N=300
#define NC_WI  3             // ceil(147/64)
#define NC_WH  5             // ceil(300/64)
#define NC_WO  7             // ceil(433/64)

// ---------------- Device scratch (static, allocation-free) ----------------
__device__ __half g_inp [(size_t)N_BONDS_MAX * H_DIM];
__device__ __half g_msgA[(size_t)N_BONDS_MAX * H_DIM];
__device__ __half g_msgB[(size_t)N_BONDS_MAX * H_DIM];
__device__ __half g_amsg[(size_t)N_ATOMS_MAX * H_DIM];
__device__ float  g_ahid[(size_t)N_ATOMS_MAX * H_DIM];
__device__ __align__(1024) uint32_t g_packWi[(size_t)MAX_CB * NC_WI * TILE_U32];
__device__ __align__(1024) uint32_t g_packWh[(size_t)MAX_CB * NC_WH * TILE_U32];
__device__ __align__(1024) uint32_t g_packWo[(size_t)MAX_CB * NC_WO * TILE_U32];

// Arch-feature gate: tcgen05 exists only in arch-specific (sm_103a) passes.
#if defined(__CUDA_ARCH_FEAT_SM103_ALL) || defined(__CUDA_ARCH_FEAT_SM100_ALL) || defined(__CUDA_ARCH_SPECIFIC__)
#define USE_TC5 1
#else
#define USE_TC5 0
#endif

// ---------------- common helpers ----------------
__device__ __forceinline__ uint32_t smem_u32(const void* p) {
    uint32_t a;
    asm("{ .reg .u64 t; cvta.to.shared.u64 t, %1; cvt.u32.u64 %0, t; }" : "=r"(a) : "l"(p));
    return a;
}
__device__ __forceinline__ uint32_t sw128(uint32_t off) { return off ^ ((off >> 3) & 0x70); }
__device__ __forceinline__ uint32_t pack_h2(float lo, float hi) {
    __half2 h = __floats2half2_rn(lo, hi);
    return *(uint32_t*)&h;
}
__device__ __forceinline__ float2 unpack_h2(uint32_t u) {
    __half2 h = *(__half2*)&u;
    return __half22float2(h);
}

#if USE_TC5
#define TMEM_COLS 128
// idesc kind::f16 (fp16 in, fp32 acc): bit4 dtype=F32 | atype=FP16(0) | btype=FP16(0)
//                                      | (N/8)@17 | (M/16)@24
#define MMA_IDESC ((1u<<4) | ((BN/8u)<<17) | ((BM/16u)<<24))

__device__ __forceinline__ bool elect_one() {
    uint32_t p;
    asm volatile("{ .reg .pred P; elect.sync _|P, 0xFFFFFFFF; selp.b32 %0, 1, 0, P; }" : "=r"(p));
    return p != 0;
}
__device__ __forceinline__ uint64_t make_desc_sw128(uint32_t addr) {
    return (uint64_t)((addr >> 4) & 0x3FFF)
         | ((uint64_t)1  << 16) | ((uint64_t)64 << 32)
         | ((uint64_t)1  << 46) | ((uint64_t)2  << 61);
}
__device__ __forceinline__ void tmem_alloc(uint32_t smem_dst, uint32_t ncols) {
    asm volatile("tcgen05.alloc.cta_group::1.sync.aligned.shared::cta.b32 [%0], %1;"
                 :: "r"(smem_dst), "r"(ncols) : "memory");
}
__device__ __forceinline__ void tmem_relinquish() {
    asm volatile("tcgen05.relinquish_alloc_permit.cta_group::1.sync.aligned;");
}
__device__ __forceinline__ void tmem_dealloc(uint32_t tmem, uint32_t ncols) {
    asm volatile("tcgen05.dealloc.cta_group::1.sync.aligned.b32 %0, %1;" :: "r"(tmem), "r"(ncols));
}
__device__ __forceinline__ void mbar_init(uint32_t mb, uint32_t cnt) {
    asm volatile("mbarrier.init.shared.b64 [%0], %1;" :: "r"(mb), "r"(cnt) : "memory");
}
__device__ __forceinline__ void mbar_expect_tx(uint32_t mb, uint32_t bytes) {
    asm volatile("mbarrier.arrive.expect_tx.shared.b64 _, [%0], %1;"
                 :: "r"(mb), "r"(bytes) : "memory");
}
__device__ __forceinline__ void bulk_copy_g2s(uint32_t dst_smem, const void* src_gmem,
                                              uint32_t bytes, uint32_t mb) {
    asm volatile("cp.async.bulk.shared::cta.global.mbarrier::complete_tx::bytes "
                 "[%0], [%1], %2, [%3];"
                 :: "r"(dst_smem), "l"(src_gmem), "r"(bytes), "r"(mb) : "memory");
}
__device__ __forceinline__ void mbar_wait(uint32_t mb, uint32_t parity) {
    asm volatile(
        "{\n\t.reg .pred P;\n\t"
        "WL_%=:\n\t"
        "mbarrier.try_wait.parity.acquire.cta.shared::cta.b64 P, [%0], %1, 0x989680;\n\t"
        "@!P bra WL_%=;\n\t}"
        :: "r"(mb), "r"(parity) : "memory");
}
__device__ __forceinline__ void mma_f16_ss(uint32_t d, uint64_t a, uint64_t b,
                                           uint32_t idesc, uint32_t en) {
    asm volatile(
        "{\n\t.reg .pred p;\n\tsetp.ne.u32 p, %4, 0;\n\t"
        "tcgen05.mma.cta_group::1.kind::f16 [%0], %1, %2, %3, {%5, %5, %5, %5}, p;\n\t}"
        :: "r"(d), "l"(a), "l"(b), "r"(idesc), "r"(en), "r"(0u) : "memory");
}
__device__ __forceinline__ void mma_commit(uint32_t mb) {
    asm volatile("tcgen05.commit.cta_group::1.mbarrier::arrive::one.shared::cluster.b64 [%0];"
                 :: "r"(mb) : "memory");
}
__device__ __forceinline__ void ldtm_x32(uint32_t* r, uint32_t tmem) {
    asm volatile(
        "tcgen05.ld.sync.aligned.32x32b.x32.b32 "
        "{%0,%1,%2,%3,%4,%5,%6,%7,%8,%9,%10,%11,%12,%13,%14,%15,"
        "%16,%17,%18,%19,%20,%21,%22,%23,%24,%25,%26,%27,%28,%29,%30,%31}, [%32];"
        : "=r"(r[0]), "=r"(r[1]), "=r"(r[2]), "=r"(r[3]), "=r"(r[4]), "=r"(r[5]), "=r"(r[6]), "=r"(r[7]),
          "=r"(r[8]), "=r"(r[9]), "=r"(r[10]), "=r"(r[11]), "=r"(r[12]), "=r"(r[13]), "=r"(r[14]), "=r"(r[15]),
          "=r"(r[16]), "=r"(r[17]), "=r"(r[18]), "=r"(r[19]), "=r"(r[20]), "=r"(r[21]), "=r"(r[22]), "=r"(r[23]),
          "=r"(r[24]), "=r"(r[25]), "=r"(r[26]), "=r"(r[27]), "=r"(r[28]), "=r"(r[29]), "=r"(r[30]), "=r"(r[31])
        : "r"(tmem));
}
__device__ __forceinline__ void tmem_wait_ld() {
    asm volatile("tcgen05.wait::ld.sync.aligned;" ::: "memory");
}
__device__ __forceinline__ void tc5_fence_after() {
    asm volatile("tcgen05.fence::after_thread_sync;" ::: "memory");
}
__device__ __forceinline__ void tc5_fence_before() {
    asm volatile("tcgen05.fence::before_thread_sync;" ::: "memory");
}
__device__ __forceinline__ void fence_proxy_async_cta() {
    asm volatile("fence.proxy.async.shared::cta;" ::: "memory");
}
#endif // USE_TC5

// ---------------- mma.sync fallback helpers (never the hot path) ----------------
#define BKF 16
#define SKF 20
__device__ __forceinline__ uint32_t f2tf(float f) {
    uint32_t u;
    asm("cvt.rna.tf32.f32 %0, %1;" : "=r"(u) : "f"(f));
    return u;
}
__device__ __forceinline__ void mma8(float* c, const uint32_t* a, const uint32_t* b) {
    asm volatile(
        "mma.sync.aligned.m16n8k8.row.col.f32.tf32.tf32.f32 "
        "{%0,%1,%2,%3}, {%4,%5,%6,%7}, {%8,%9}, {%0,%1,%2,%3};\n"
        : "+f"(c[0]), "+f"(c[1]), "+f"(c[2]), "+f"(c[3])
        : "r"(a[0]), "r"(a[1]), "r"(a[2]), "r"(a[3]), "r"(b[0]), "r"(b[1]));
}

// ---- Pack W[K][N] (fp32) into swizzled fp16 tiles: 128 n-rows x 32 half2 ----
__global__ void pack_W_kernel(const float* __restrict__ W, uint32_t* __restrict__ dst,
                              int K, int N, int NC)
{
    const int tile = blockIdx.x;          // cb * NC + ci
    const int cb = tile / NC, ci = tile - cb * NC;
    const int colBase = cb * BN, kk = ci * KC;
    uint32_t* out = dst + (size_t)tile * TILE_U32;
    for (int i = threadIdx.x; i < TILE_U32; i += blockDim.x) {
        const int n = i >> 5, k2 = i & 31;
        const int gc = colBase + n;
        const int gk0 = kk + 2 * k2, gk1 = gk0 + 1;
        float v0 = (gk0 < K && gc < N) ? W[(size_t)gk0 * N + gc] : 0.f;
        float v1 = (gk1 < K && gc < N) ? W[(size_t)gk1 * N + gc] : 0.f;
        out[sw128((uint32_t)(n << 7) + (uint32_t)(k2 << 2)) >> 2] = pack_h2(v0, v1);
    }
}

// ---------------- Unified GEMM (fp16 pipeline) ----------------
// MODE 0: out_h = (A0f @ W)            A0f fp32, out half (inp)
// MODE 1: out_h = relu(aux_h + (A0h[b2a] - ra1(A1h[b2revb])) @ W)   half in/out
// MODE 2: out_f = relu([A0f | A1h] @ W + bias)                      ahid fp32
template<int MODE, int RELU_A1>
__global__ __launch_bounds__(NTHR, 4)
void gemm_tc5(const float* __restrict__ A0f, const __half* __restrict__ A0h,
              const __half* __restrict__ A1h,
              const int* __restrict__ b2a, const int* __restrict__ b2revb,
              const float* __restrict__ W, const uint32_t* __restrict__ Wp,
              const __half* __restrict__ aux_h, const float* __restrict__ bias,
              __half* __restrict__ out_h, float* __restrict__ out_f,
              int M, int K, int N, int AF)
{
    const int tid  = threadIdx.x;
    const int lane = tid & 31;
    const int wid  = tid >> 5;
    const int rowBase = blockIdx.y * BM;
    const int colBase = blockIdx.x * BN;

    __shared__ const float*  s_pf[BM];   // fp32 sources (MODE 0/2)
    __shared__ const __half* s_p0[BM];   // half sources
    __shared__ const __half* s_p1[BM];
    if (tid < BM) {
        int gr = rowBase + tid;
        if (gr >= M) gr = M - 1;
        if (MODE == 0) {
            s_pf[tid] = A0f + (size_t)gr * K;
        } else if (MODE == 1) {
            s_p0[tid] = A0h + (size_t)b2a[gr] * K;
            s_p1[tid] = A1h + (size_t)b2revb[gr] * K;
        } else {
            s_pf[tid] = A0f + (size_t)gr * AF;
            s_p1[tid] = A1h + (size_t)gr * (K - AF);
        }
    }

#if USE_TC5
    // ====== tcgen05 f16: reg-prefetched A (two streams) + TMA packed B ======
    __shared__ alignas(1024) uint32_t sA[BM * KC2];   // 16 KB (128 x 64 halfs)
    __shared__ alignas(1024) uint32_t sB[BN * KC2];   // 16 KB
    __shared__ uint32_t s_tmem;
    __shared__ alignas(8) uint64_t s_mbar_mma;
    __shared__ alignas(8) uint64_t s_mbar_tma;

    if (wid == 0) {
        tmem_alloc(smem_u32(&s_tmem), TMEM_COLS);
        tmem_relinquish();
    }
    if (tid == 0) {
        mbar_init(smem_u32(&s_mbar_mma), 1);
        mbar_init(smem_u32(&s_mbar_tma), 1);
    }
    __syncthreads();

    const uint32_t tmem = s_tmem;
    const uint32_t mbM  = smem_u32(&s_mbar_mma);
    const uint32_t mbT  = smem_u32(&s_mbar_tma);
    const uint32_t sB_addr = smem_u32(sB);
    const uint64_t adesc = make_desc_sw128(smem_u32(sA));
    const uint64_t bdesc = make_desc_sw128(sB_addr);

    uint32_t phM = 0, phT = 0;
    const int NC = (K + KC - 1) / KC;
    const uint32_t* wp = Wp + (size_t)blockIdx.x * NC * TILE_U32;
    const int K2 = K >> 1;   // half2 count per row (MODE 1: K=300 even)

    // conflict-free swizzled store index (proof: off[7:9] = wid)
    const uint32_t sa_lane = (uint32_t)(lane ^ (wid << 2));

    // ---- A prefetch: 16 half2 regs per stream; rows r = p*8 + wid, half2-col = c2 ----
    uint32_t ra[16];   // MODE 1: p0 half2 | MODE 0/2: packed half2 built from fp32/half
    uint32_t rb[16];   // MODE 1 only: p1 half2
    {
        const int c2 = lane;   // chunk 0
        if (MODE == 1) {
            const bool ok = c2 < K2;
            #pragma unroll
            for (int p = 0; p < 16; ++p) {
                const int r = (p << 3) + wid;
                ra[p] = ok ? ((const uint32_t*)s_p0[r])[c2] : 0u;
            }
            #pragma unroll
            for (int p = 0; p < 16; ++p) {
                const int r = (p << 3) + wid;
                rb[p] = ok ? ((const uint32_t*)s_p1[r])[c2] : 0u;
            }
        } else {
            const int e0 = 2 * c2, e1 = e0 + 1;
            #pragma unroll
            for (int p = 0; p < 16; ++p) {
                const int r = (p << 3) + wid;
                float v0 = 0.f, v1 = 0.f;
                if (MODE == 0) {
                    if (e0 < K) v0 = s_pf[r][e0];
                    if (e1 < K) v1 = s_pf[r][e1];
                } else {
                    if (e0 < K) v0 = (e0 < AF) ? s_pf[r][e0] : __half2float(s_p1[r][e0 - AF]);
                    if (e1 < K) v1 = (e1 < AF) ? s_pf[r][e1] : __half2float(s_p1[r][e1 - AF]);
                }
                ra[p] = pack_h2(v0, v1);
            }
        }
    }

    for (int ci = 0; ci < NC; ++ci) {
        if (ci > 0) { mbar_wait(mbM, phM); phM ^= 1u; }   // sA/sB free

        // ---- issue async bulk copy of pre-packed B tile ----
        if (wid == 0 && elect_one()) {
            mbar_expect_tx(mbT, TILE_BYTES);
            bulk_copy_g2s(sB_addr, wp + (size_t)ci * TILE_U32, TILE_BYTES, mbT);
        }

        // ---- write prefetched A regs -> smem (diff/relu folded for MODE 1) ----
        #pragma unroll
        for (int p = 0; p < 16; ++p) {
            const int r = (p << 3) + wid;
            uint32_t v;
            if (MODE == 1) {
                float2 a = unpack_h2(ra[p]);
                float2 b = unpack_h2(rb[p]);
                if (RELU_A1) { b.x = fmaxf(b.x, 0.f); b.y = fmaxf(b.y, 0.f); }
                v = pack_h2(a.x - b.x, a.y - b.y);
            } else {
                v = ra[p];
            }
            sA[((uint32_t)r << 5) + sa_lane] = v;
        }

        // ---- issue next A-chunk loads NOW (overlaps TMA wait + MMA) ----
        if (ci + 1 < NC) {
            const int c2 = (ci + 1) * KC2 + lane;
            if (MODE == 1) {
                const bool ok = c2 < K2;
                #pragma unroll
                for (int p = 0; p < 16; ++p) {
                    const int r = (p << 3) + wid;
                    ra[p] = ok ? ((const uint32_t*)s_p0[r])[c2] : 0u;
                }
                #pragma unroll
                for (int p = 0; p < 16; ++p) {
                    const int r = (p << 3) + wid;
                    rb[p] = ok ? ((const uint32_t*)s_p1[r])[c2] : 0u;
                }
            } else {
                const int e0 = 2 * c2, e1 = e0 + 1;
                #pragma unroll
                for (int p = 0; p < 16; ++p) {
                    const int r = (p << 3) + wid;
                    float v0 = 0.f, v1 = 0.f;
                    if (MODE == 0) {
                        if (e0 < K) v0 = s_pf[r][e0];
                        if (e1 < K) v1 = s_pf[r][e1];
                    } else {
                        if (e0 < K) v0 = (e0 < AF) ? s_pf[r][e0] : __half2float(s_p1[r][e0 - AF]);
                        if (e1 < K) v1 = (e1 < AF) ? s_pf[r][e1] : __half2float(s_p1[r][e1 - AF]);
                    }
                    ra[p] = pack_h2(v0, v1);
                }
            }
        }

        // ---- wait for B tile, then sync A visibility ----
        mbar_wait(mbT, phT); phT ^= 1u;
        __syncthreads();

        if (wid == 0) {
            fence_proxy_async_cta();
            if (elect_one()) {
                #pragma unroll
                for (int ks = 0; ks < 4; ++ks) {   // K=16 per mma, 4 per 64-chunk
                    const uint32_t en = (ci > 0 || ks > 0) ? 1u : 0u;
                    mma_f16_ss(tmem, adesc + (uint64_t)(ks * 2), bdesc + (uint64_t)(ks * 2),
                               MMA_IDESC, en);
                }
                mma_commit(mbM);
            }
        }
    }

    mbar_wait(mbM, phM);

    // ---- epilogue: warp w -> rows (w&3)*32+lane ; cols (w>>2)*64..+63 ----
    tc5_fence_after();
    const int gr = rowBase + (wid & 3) * 32 + lane;
    const bool rok = gr < M;
    const int cb0 = (wid >> 2) * 2;

    #pragma unroll
    for (int bb = 0; bb < 2; ++bb) {
        const int b = cb0 + bb;
        uint32_t d[32];
        ldtm_x32(d, tmem + (uint32_t)(b * 32));
        tmem_wait_ld();
        if (rok) {
            const int cbase = colBase + b * 32;
            #pragma unroll
            for (int j = 0; j < 32; j += 4) {
                const int c = cbase + j;
                if (c + 3 < N) {
                    const size_t o = (size_t)gr * N + c;
                    float v0 = __uint_as_float(d[j]),   v1 = __uint_as_float(d[j+1]);
                    float v2 = __uint_as_float(d[j+2]), v3 = __uint_as_float(d[j+3]);
                    if (MODE == 0) {
                        uint2 u;
                        u.x = pack_h2(v0, v1);
                        u.y = pack_h2(v2, v3);
                        *(uint2*)(out_h + o) = u;
                    } else if (MODE == 1) {
                        uint2 iu = *(const uint2*)(aux_h + o);
                        float2 i0 = unpack_h2(iu.x), i1 = unpack_h2(iu.y);
                        uint2 u;
                        u.x = pack_h2(fmaxf(i0.x + v0, 0.f), fmaxf(i0.y + v1, 0.f));
                        u.y = pack_h2(fmaxf(i1.x + v2, 0.f), fmaxf(i1.y + v3, 0.f));
                        *(uint2*)(out_h + o) = u;
                    } else {
                        *(float4*)(out_f + o) = make_float4(
                            fmaxf(v0 + bias[c],   0.f), fmaxf(v1 + bias[c+1], 0.f),
                            fmaxf(v2 + bias[c+2], 0.f), fmaxf(v3 + bias[c+3], 0.f));
                    }
                } else {
                    #pragma unroll
                    for (int q = 0; q < 4; ++q) {
                        const int cc = c + q;
                        if (cc >= N) break;
                        const size_t o = (size_t)gr * N + cc;
                        const float v = __uint_as_float(d[j + q]);
                        if (MODE == 0)      { out_h[o] = __float2half_rn(v); }
                        else if (MODE == 1) { out_h[o] = __float2half_rn(fmaxf(__half2float(aux_h[o]) + v, 0.f)); }
                        else                { out_f[o] = fmaxf(v + bias[cc], 0.f); }
                    }
                }
            }
        }
    }
    tc5_fence_before();
    __syncthreads();
    if (wid == 0) tmem_dealloc(tmem, TMEM_COLS);

#else
    // ================= mma.sync tf32 fallback (half-stored data) =================
    __shared__ uint32_t As[BM][SKF];
    __shared__ uint32_t Bs[BN][SKF];
    __syncthreads();

    const int wm = wid >> 2, wn = wid & 3;
    const int g = lane >> 2, tg = lane & 3;

    float acc[4][4][4] = {};

    const int arow = tid >> 1;
    const int acb  = (tid & 1) * 8;

    for (int kk = 0; kk < K; kk += BKF) {
        #pragma unroll
        for (int j = 0; j < 8; ++j) {
            int gk = kk + acb + j;
            float v = 0.f;
            if (gk < K) {
                if (MODE == 0)      v = s_pf[arow][gk];
                else if (MODE == 1) {
                    float a1 = __half2float(s_p1[arow][gk]);
                    if (RELU_A1) a1 = fmaxf(a1, 0.f);
                    v = __half2float(s_p0[arow][gk]) - a1;
                }
                else v = (gk < AF) ? s_pf[arow][gk] : __half2float(s_p1[arow][gk - AF]);
            }
            As[arow][acb + j] = f2tf(v);
        }
        {
            int bk = tid >> 4;
            int nb = (tid & 15) * 8;
            int gk = kk + bk;
            bool kok = gk < K;
            const float* src = W + (size_t)(kok ? gk : 0) * N;
            #pragma unroll
            for (int j = 0; j < 8; ++j) {
                int gc = colBase + nb + j;
                float v = (kok && gc < N) ? src[gc] : 0.f;
                Bs[nb + j][bk] = f2tf(v);
            }
        }
        __syncthreads();
        #pragma unroll
        for (int ks = 0; ks < BKF; ks += 8) {
            uint32_t af[4][4], bf[4][2];
            #pragma unroll
            for (int mi = 0; mi < 4; ++mi) {
                int r = wm * 64 + mi * 16 + g;
                af[mi][0] = As[r][ks + tg];
                af[mi][1] = As[r + 8][ks + tg];
                af[mi][2] = As[r][ks + tg + 4];
                af[mi][3] = As[r + 8][ks + tg + 4];
            }
            #pragma unroll
            for (int ni = 0; ni < 4; ++ni) {
                int c = wn * 32 + ni * 8 + g;
                bf[ni][0] = Bs[c][ks + tg];
                bf[ni][1] = Bs[c][ks + tg + 4];
            }
            #pragma unroll
            for (int mi = 0; mi < 4; ++mi)
                #pragma unroll
                for (int ni = 0; ni < 4; ++ni)
                    mma8(acc[mi][ni], af[mi], bf[ni]);
        }
        __syncthreads();
    }

    #pragma unroll
    for (int mi = 0; mi < 4; ++mi) {
        int r0 = rowBase + wm * 64 + mi * 16 + g;
        #pragma unroll
        for (int ni = 0; ni < 4; ++ni) {
            int c0 = colBase + wn * 32 + ni * 8 + 2 * tg;
            if (c0 >= N) continue;
            #pragma unroll
            for (int hh = 0; hh < 2; ++hh) {
                int rr = r0 + hh * 8;
                if (rr >= M) continue;
                size_t o = (size_t)rr * N + c0;
                float v0 = acc[mi][ni][hh*2], v1 = acc[mi][ni][hh*2+1];
                bool c1 = (c0 + 1) < N;
                if (MODE == 0) {
                    out_h[o] = __float2half_rn(v0);
                    if (c1) out_h[o+1] = __float2half_rn(v1);
                } else if (MODE == 1) {
                    out_h[o] = __float2half_rn(fmaxf(__half2float(aux_h[o]) + v0, 0.f));
                    if (c1) out_h[o+1] = __float2half_rn(fmaxf(__half2float(aux_h[o+1]) + v1, 0.f));
                } else {
                    out_f[o] = fmaxf(v0 + bias[c0], 0.f);
                    if (c1) out_f[o+1] = fmaxf(v1 + bias[c0+1], 0.f);
                }
            }
        }
    }
#endif
}

// ---- Gather: amsg[a] = sum_nb ra(msg[a2b[a][nb]]) ; fp32 accumulate, half I/O ----
template<int RELU>
__global__ void gather_atoms_kernel(const __half* __restrict__ msg, const int* __restrict__ a2b,
                                    __half* __restrict__ amsg, int n_atoms, int max_nb)
{
    const int H4 = H_DIM / 4;   // 75 chunks of 4 halfs (8B)
    int idx = blockIdx.x * blockDim.x + threadIdx.x;
    int total = n_atoms * H4;
    if (idx >= total) return;
    int atom = idx / H4;
    int h4   = idx - atom * H4;
    float s0 = 0.f, s1 = 0.f, s2 = 0.f, s3 = 0.f;
    for (int nb = 0; nb < max_nb; ++nb) {
        int b = __ldg(&a2b[(size_t)atom * max_nb + nb]);
        uint2 u = *((const uint2*)(msg + (size_t)b * H_DIM) + h4);
        float2 v0 = unpack_h2(u.x), v1 = unpack_h2(u.y);
        if (RELU) {
            v0.x = fmaxf(v0.x, 0.f); v0.y = fmaxf(v0.y, 0.f);
            v1.x = fmaxf(v1.x, 0.f); v1.y = fmaxf(v1.y, 0.f);
        }
        s0 += v0.x; s1 += v0.y; s2 += v1.x; s3 += v1.y;
    }
    uint2 o;
    o.x = pack_h2(s0, s1);
    o.y = pack_h2(s2, s3);
    *((uint2*)amsg + idx) = o;
}

// ---- Segment mean over sorted mol ids (fp32) ----
__global__ void segmean_kernel(const float* __restrict__ ahid, const int* __restrict__ atom_mol,
                               float* __restrict__ out, int n_atoms, int Hh)
{
    const int m = blockIdx.x;
    __shared__ int s_bounds[2];
    if (threadIdx.x == 0) {
        int lo = 0, hi = n_atoms;
        while (lo < hi) { int mid = (lo + hi) >> 1; if (atom_mol[mid] < m) lo = mid + 1; else hi = mid; }
        s_bounds[0] = lo;
        hi = n_atoms;
        while (lo < hi) { int mid = (lo + hi) >> 1; if (atom_mol[mid] < m + 1) lo = mid + 1; else hi = mid; }
        s_bounds[1] = lo;
    }
    __syncthreads();
    const int start = s_bounds[0], end = s_bounds[1];
    const float inv = (end > start) ? 1.f / (float)(end - start) : 0.f;
    for (int h = threadIdx.x; h < Hh; h += blockDim.x) {
        float s = 0.f;
        for (int a = start; a < end; ++a) s += ahid[(size_t)a * Hh + h];
        out[(size_t)m * Hh + h] = s * inv;
    }
}

// ---------------- Launch ----------------
extern "C" void kernel_launch(void* const* d_in, const int* in_sizes, int n_in,
                              void* d_out, int out_size)
{
    const float* f_atoms = (const float*)d_in[0];
    const float* f_bonds = (const float*)d_in[1];
    const float* W_i     = (const float*)d_in[2];
    const float* W_h     = (const float*)d_in[3];
    const float* W_o     = (const float*)d_in[4];
    const float* b_o     = (const float*)d_in[5];
    const int*   a2b     = (const int*)d_in[6];
    const int*   b2a     = (const int*)d_in[7];
    const int*   b2revb  = (const int*)d_in[8];
    const int*   atom_mol= (const int*)d_in[9];

    const int H       = in_sizes[5];             // 300
    const int n_bonds = in_sizes[7];             // 200000
    const int n_atoms = in_sizes[9];             // 100000
    const int BF      = in_sizes[1] / n_bonds;   // 147
    const int AF      = in_sizes[0] / n_atoms;   // 133
    const int max_nb  = in_sizes[6] / n_atoms;   // 6
    const int n_mols  = out_size / H;            // 4000

    __half* inp  = nullptr; cudaGetSymbolAddress((void**)&inp,  g_inp);
    __half* msgA = nullptr; cudaGetSymbolAddress((void**)&msgA, g_msgA);
    __half* msgB = nullptr; cudaGetSymbolAddress((void**)&msgB, g_msgB);
    __half* amsg = nullptr; cudaGetSymbolAddress((void**)&amsg, g_amsg);
    float*  ahid = nullptr; cudaGetSymbolAddress((void**)&ahid, g_ahid);
    uint32_t* pWi = nullptr; cudaGetSymbolAddress((void**)&pWi, g_packWi);
    uint32_t* pWh = nullptr; cudaGetSymbolAddress((void**)&pWh, g_packWh);
    uint32_t* pWo = nullptr; cudaGetSymbolAddress((void**)&pWo, g_packWo);

    dim3 blk(NTHR);
    dim3 grid_b((H + BN - 1) / BN, (n_bonds + BM - 1) / BM);   // (3, 1563)
    dim3 grid_a((H + BN - 1) / BN, (n_atoms + BM - 1) / BM);   // (3, 782)

    const int cbN   = (H + BN - 1) / BN;           // 3
    const int ncWi  = (BF + KC - 1) / KC;          // 3
    const int ncWh  = (H + KC - 1) / KC;           // 5
    const int ncWo  = (AF + H + KC - 1) / KC;      // 7

    const int thr = 256;
    int gatherBlocks = (n_atoms * (H / 4) + thr - 1) / thr;

    // launches 1-3: pack weights into swizzled fp16 tiles (tiny)
    pack_W_kernel<<<cbN * ncWi, thr>>>(W_i, pWi, BF, H, ncWi);
    pack_W_kernel<<<cbN * ncWh, thr>>>(W_h, pWh, H, H, ncWh);
    pack_W_kernel<<<cbN * ncWo, thr>>>(W_o, pWo, AF + H, H, ncWo);

    // launch 4: inp(half) = f_bonds @ W_i   (relu fused into consumers)
    gemm_tc5<0,0><<<grid_b, blk>>>(f_bonds, nullptr, nullptr, nullptr, nullptr,
                                   W_i, pWi, nullptr, nullptr,
                                   inp, nullptr, n_bonds, BF, H, 0);

    // launches 5-6: depth 1   (launch 6 = gemm_h<1,1> -> profiled by ncu -s 5 -c 1)
    gather_atoms_kernel<1><<<gatherBlocks, thr>>>(inp, a2b, amsg, n_atoms, max_nb);
    gemm_tc5<1,1><<<grid_b, blk>>>(nullptr, amsg, inp, b2a, b2revb,
                                   W_h, pWh, inp, nullptr,
                                   msgB, nullptr, n_bonds, H, H, 0);

    // launches 7-8: depth 2
    gather_atoms_kernel<0><<<gatherBlocks, thr>>>(msgB, a2b, amsg, n_atoms, max_nb);
    gemm_tc5<1,0><<<grid_b, blk>>>(nullptr, amsg, msgB, b2a, b2revb,
                                   W_h, pWh, inp, nullptr,
                                   msgA, nullptr, n_bonds, H, H, 0);

    // launch 9: final atom aggregation
    gather_atoms_kernel<0><<<gatherBlocks, thr>>>(msgA, a2b, amsg, n_atoms, max_nb);

    // launch 10: readout (fp32 out)
    gemm_tc5<2,0><<<grid_a, blk>>>(f_atoms, nullptr, amsg, nullptr, nullptr,
                                   W_o, pWo, nullptr, b_o,
                                   nullptr, ahid, n_atoms, AF + H, H, AF);

    // launch 11: per-molecule mean
    segmean_kernel<<<n_mols, 256>>>(ahid, atom_mol, (float*)d_out, n_atoms, H);
}